// round 1
// baseline (speedup 1.0000x reference)
#include <cuda_runtime.h>
#include <cstdint>
#include <cstddef>

// Problem constants
#define T_SEQ 2048
#define C_EMB 512
#define NB 4
#define NHD 8
#define HD 64
#define BH (NB*NHD)
#define M_ROWS (NB*T_SEQ)   // 8192

// ---------------- scratch layout (one __device__ symbol, no allocations) ----
constexpr size_t SZ_H   = (size_t)M_ROWS * C_EMB;        // 4M floats
constexpr size_t SZ_WP  = (size_t)C_EMB * 1536;          // packed QKV weights
constexpr size_t SZ_QKV = (size_t)BH * T_SEQ * HD;       // 4M floats each
constexpr size_t SZ_S   = (size_t)BH * T_SEQ * T_SEQ;    // 134M floats (512MB)
constexpr size_t SZ_COL = (size_t)BH * T_SEQ;
constexpr size_t SZ_FF  = (size_t)M_ROWS * 4 * C_EMB;    // 16.8M floats

constexpr size_t OFF_H  = 0;
constexpr size_t OFF_WP = OFF_H  + SZ_H;
constexpr size_t OFF_Q  = OFF_WP + SZ_WP;
constexpr size_t OFF_K  = OFF_Q  + SZ_QKV;
constexpr size_t OFF_V  = OFF_K  + SZ_QKV;
constexpr size_t OFF_S  = OFF_V  + SZ_QKV;
constexpr size_t OFF_M  = OFF_S  + SZ_S;
constexpr size_t OFF_L  = OFF_M  + SZ_COL;
constexpr size_t OFF_AO = OFF_L  + SZ_COL;
constexpr size_t OFF_X2 = OFF_AO + SZ_H;
constexpr size_t OFF_H2 = OFF_X2 + SZ_H;
constexpr size_t OFF_FF = OFF_H2 + SZ_H;
constexpr size_t SZ_TOTAL = OFF_FF + SZ_FF;

__device__ float g_scratch[SZ_TOTAL];

// ---------------- LayerNorm: one block (256 thr) per row of 512 -------------
__global__ __launch_bounds__(256) void ln_kernel(
    const float* __restrict__ x, const float* __restrict__ g,
    const float* __restrict__ be, float* __restrict__ o)
{
    const int row = blockIdx.x;
    const float* xr = x + (size_t)row * C_EMB;
    const int t = threadIdx.x;
    float a = xr[t], b = xr[t + 256];
    float s  = a + b;
    float sq = a * a + b * b;
    #pragma unroll
    for (int off = 16; off; off >>= 1) {
        s  += __shfl_xor_sync(0xffffffffu, s,  off);
        sq += __shfl_xor_sync(0xffffffffu, sq, off);
    }
    __shared__ float sh[16];
    const int w = t >> 5;
    if ((t & 31) == 0) { sh[w] = s; sh[8 + w] = sq; }
    __syncthreads();
    if (t == 0) {
        float S = 0.f, Q = 0.f;
        #pragma unroll
        for (int i = 0; i < 8; i++) { S += sh[i]; Q += sh[8 + i]; }
        sh[0] = S; sh[8] = Q;
    }
    __syncthreads();
    const float mu  = sh[0] * (1.f / 512.f);
    const float var = sh[8] * (1.f / 512.f) - mu * mu;
    const float inv = rsqrtf(var + 1e-5f);
    o[(size_t)row * C_EMB + t]       = (a - mu) * inv * g[t]       + be[t];
    o[(size_t)row * C_EMB + t + 256] = (b - mu) * inv * g[t + 256] + be[t + 256];
}

// ---------------- pack Wq/Wk/Wv [H,C,D] -> Wpack [C, 1536] ------------------
__global__ void pack_kernel(const float* __restrict__ Wq, const float* __restrict__ Wk,
                            const float* __restrict__ Wv, float* __restrict__ wp)
{
    int idx = blockIdx.x * blockDim.x + threadIdx.x;
    if (idx >= C_EMB * C_EMB) return;
    int c = idx / C_EMB;
    int n = idx % C_EMB;       // n = h*64 + d
    int h = n >> 6, d = n & 63;
    size_t src = ((size_t)h * C_EMB + c) * HD + d;
    wp[(size_t)c * 1536 + n]        = Wq[src];
    wp[(size_t)c * 1536 + 512 + n]  = Wk[src];
    wp[(size_t)c * 1536 + 1024 + n] = Wv[src];
}

// ---------------- generic tiled SGEMM: C = A[MxK] @ B[KxN] ------------------
// BM=128, BN=64, BK=16, 256 threads, 8x4 micro-tile.
// MODE 0: plain   MODE 1: +bias[n]+res   MODE 2: relu(+bias)   MODE 3: QKV scatter
template<int MODE>
__global__ __launch_bounds__(256) void gemm_kernel(
    const float* __restrict__ A, const float* __restrict__ B, float* __restrict__ C,
    int M, int N, int K,
    const float* __restrict__ bias, const float* __restrict__ res,
    float* __restrict__ Cq, float* __restrict__ Ck, float* __restrict__ Cv)
{
    __shared__ float As[128][17];
    __shared__ __align__(16) float Bs[16][68];
    const int tid = threadIdx.x;
    const int m0 = blockIdx.y * 128;
    const int n0 = blockIdx.x * 64;
    const int ty = tid >> 4;        // 0..15
    const int tx = tid & 15;        // 0..15
    const int arow_base = tid >> 2; // 0..63
    const int acol = (tid & 3) << 2;
    const int brow = tid >> 4;
    const int bcol = (tid & 15) << 2;

    float acc[8][4];
    #pragma unroll
    for (int i = 0; i < 8; i++)
        #pragma unroll
        for (int j = 0; j < 4; j++) acc[i][j] = 0.f;

    for (int k0 = 0; k0 < K; k0 += 16) {
        #pragma unroll
        for (int p = 0; p < 2; ++p) {
            int ar = arow_base + p * 64;
            float4 av = *reinterpret_cast<const float4*>(A + (size_t)(m0 + ar) * K + k0 + acol);
            As[ar][acol + 0] = av.x; As[ar][acol + 1] = av.y;
            As[ar][acol + 2] = av.z; As[ar][acol + 3] = av.w;
        }
        {
            float4 bv = *reinterpret_cast<const float4*>(B + (size_t)(k0 + brow) * N + n0 + bcol);
            Bs[brow][bcol + 0] = bv.x; Bs[brow][bcol + 1] = bv.y;
            Bs[brow][bcol + 2] = bv.z; Bs[brow][bcol + 3] = bv.w;
        }
        __syncthreads();
        #pragma unroll
        for (int k = 0; k < 16; k++) {
            float a[8];
            #pragma unroll
            for (int i = 0; i < 8; i++) a[i] = As[ty * 8 + i][k];
            float4 b4 = *reinterpret_cast<const float4*>(&Bs[k][tx * 4]);
            float b[4] = {b4.x, b4.y, b4.z, b4.w};
            #pragma unroll
            for (int i = 0; i < 8; i++)
                #pragma unroll
                for (int j = 0; j < 4; j++)
                    acc[i][j] = fmaf(a[i], b[j], acc[i][j]);
        }
        __syncthreads();
    }

    #pragma unroll
    for (int i = 0; i < 8; i++) {
        const int m = m0 + ty * 8 + i;
        #pragma unroll
        for (int j = 0; j < 4; j++) {
            const int n = n0 + tx * 4 + j;
            float v = acc[i][j];
            if (MODE == 0) {
                C[(size_t)m * N + n] = v;
            } else if (MODE == 1) {
                C[(size_t)m * N + n] = v + bias[n] + res[(size_t)m * N + n];
            } else if (MODE == 2) {
                C[(size_t)m * N + n] = fmaxf(v + bias[n], 0.f);
            } else { // QKV scatter: n -> (which, h, d), m -> (b, t); dst layout [BH,T,D]
                int which = n >> 9, nn = n & 511;
                int h = nn >> 6, d = nn & 63;
                int b = m >> 11, t = m & 2047;
                float* dst = (which == 0) ? Cq : ((which == 1) ? Ck : Cv);
                dst[(((size_t)(b * NHD + h)) * T_SEQ + t) * HD + d] = v;
            }
        }
    }
}

// ---------------- attention scores: S[t,s] = scale * q.k, causal-masked -----
__global__ __launch_bounds__(256) void score_kernel(
    const float* __restrict__ q, const float* __restrict__ kmat, float* __restrict__ S)
{
    const int tt = blockIdx.x;   // t tile
    const int st = blockIdx.y;   // s tile
    const int bh = blockIdx.z;
    if (st > tt) return;         // strictly-upper tiles never written/read

    __shared__ float Qs[64][65];
    __shared__ float Ks[64][65];
    const int tid = threadIdx.x;
    const float* qb = q    + ((size_t)bh * T_SEQ + tt * 64) * HD;
    const float* kb = kmat + ((size_t)bh * T_SEQ + st * 64) * HD;
    const int r4 = tid >> 6, c = tid & 63;
    #pragma unroll
    for (int p = 0; p < 16; ++p) {
        int row = p * 4 + r4;
        Qs[row][c] = qb[row * HD + c];
        Ks[row][c] = kb[row * HD + c];
    }
    __syncthreads();

    const int ty = tid >> 4, tx = tid & 15;
    float acc[4][4];
    #pragma unroll
    for (int i = 0; i < 4; i++)
        #pragma unroll
        for (int j = 0; j < 4; j++) acc[i][j] = 0.f;

    #pragma unroll 16
    for (int k = 0; k < 64; k++) {
        float a[4], b[4];
        #pragma unroll
        for (int i = 0; i < 4; i++) a[i] = Qs[ty * 4 + i][k];
        #pragma unroll
        for (int j = 0; j < 4; j++) b[j] = Ks[tx * 4 + j][k];
        #pragma unroll
        for (int i = 0; i < 4; i++)
            #pragma unroll
            for (int j = 0; j < 4; j++)
                acc[i][j] = fmaf(a[i], b[j], acc[i][j]);
    }

    const float scale = 0.04419417382415922f;  // 512^-0.5
    float* Sb = S + (size_t)bh * T_SEQ * T_SEQ;
    #pragma unroll
    for (int i = 0; i < 4; i++) {
        const int t = tt * 64 + ty * 4 + i;
        #pragma unroll
        for (int j = 0; j < 4; j++) {
            const int s = st * 64 + tx * 4 + j;
            float v = acc[i][j] * scale;
            if (s > t) v = -1e30f;               // mask (finite: avoids inf-inf NaN)
            Sb[(size_t)t * T_SEQ + s] = v;
        }
    }
}

// ---------------- per-KEY-column softmax stats (online max/sum over t) ------
__global__ __launch_bounds__(256) void colstats_kernel(
    const float* __restrict__ S, float* __restrict__ mcol, float* __restrict__ lcol)
{
    const int bh = blockIdx.y;
    const int s  = blockIdx.x * 256 + threadIdx.x;
    const float* Sb = S + (size_t)bh * T_SEQ * T_SEQ;
    const int t0 = s & ~63;      // first written row for this column
    float mx = -3.4e38f, sum = 0.f;
    for (int t = t0; t < T_SEQ; ++t) {
        float v = Sb[(size_t)t * T_SEQ + s];
        if (v > mx) { sum = sum * __expf(mx - v) + 1.f; mx = v; }
        else        { sum += __expf(v - mx); }
    }
    mcol[(size_t)bh * T_SEQ + s] = mx;
    lcol[(size_t)bh * T_SEQ + s] = 1.f / sum;
}

// ---------------- out = P @ V, P = exp(S - m[s]) * linv[s], s <= t ----------
__global__ __launch_bounds__(256) void pv_kernel(
    const float* __restrict__ S, const float* __restrict__ V,
    const float* __restrict__ mcol, const float* __restrict__ lcol,
    float* __restrict__ ao)
{
    const int tt = blockIdx.x;
    const int bh = blockIdx.z;
    __shared__ float Ps[64][65];                   // [s_local][t_local]
    __shared__ __align__(16) float Vs[64][68];     // [s_local][d]
    const int tid = threadIdx.x;
    const float* Sb = S    + (size_t)bh * T_SEQ * T_SEQ;
    const float* mb = mcol + (size_t)bh * T_SEQ;
    const float* lb = lcol + (size_t)bh * T_SEQ;
    const int ty = tid >> 4, tx = tid & 15;
    const int r4 = tid >> 6, c = tid & 63;

    float acc[4][4];
    #pragma unroll
    for (int i = 0; i < 4; i++)
        #pragma unroll
        for (int j = 0; j < 4; j++) acc[i][j] = 0.f;

    for (int st = 0; st <= tt; ++st) {
        const int s = st * 64 + c;
        const float ms = mb[s];
        const float ls = lb[s];
        #pragma unroll
        for (int p = 0; p < 16; ++p) {
            const int row = p * 4 + r4;
            float z = Sb[(size_t)(tt * 64 + row) * T_SEQ + s];
            Ps[c][row] = __expf(z - ms) * ls;
            Vs[row][c] = V[((size_t)bh * T_SEQ + st * 64 + row) * HD + c];
        }
        __syncthreads();
        #pragma unroll 16
        for (int k = 0; k < 64; k++) {
            float a[4];
            #pragma unroll
            for (int i = 0; i < 4; i++) a[i] = Ps[k][ty * 4 + i];
            float4 b4 = *reinterpret_cast<const float4*>(&Vs[k][tx * 4]);
            float b[4] = {b4.x, b4.y, b4.z, b4.w};
            #pragma unroll
            for (int i = 0; i < 4; i++)
                #pragma unroll
                for (int j = 0; j < 4; j++)
                    acc[i][j] = fmaf(a[i], b[j], acc[i][j]);
        }
        __syncthreads();
    }

    const int b = bh >> 3, h = bh & 7;
    #pragma unroll
    for (int i = 0; i < 4; i++) {
        const int t = tt * 64 + ty * 4 + i;
        #pragma unroll
        for (int j = 0; j < 4; j++) {
            ao[(size_t)(b * T_SEQ + t) * C_EMB + h * HD + tx * 4 + j] = acc[i][j];
        }
    }
}

// ---------------- launcher ---------------------------------------------------
extern "C" void kernel_launch(void* const* d_in, const int* in_sizes, int n_in,
                              void* d_out, int out_size)
{
    const float* x     = (const float*)d_in[0];
    const float* Wq    = (const float*)d_in[1];
    const float* Wk    = (const float*)d_in[2];
    const float* Wv    = (const float*)d_in[3];
    const float* Wo    = (const float*)d_in[4];
    const float* bo    = (const float*)d_in[5];
    const float* W1    = (const float*)d_in[6];
    const float* b1    = (const float*)d_in[7];
    const float* W2    = (const float*)d_in[8];
    const float* b2    = (const float*)d_in[9];
    const float* g1    = (const float*)d_in[10];
    const float* beta1 = (const float*)d_in[11];
    const float* g2    = (const float*)d_in[12];
    const float* beta2 = (const float*)d_in[13];
    float* out = (float*)d_out;

    void* sp = nullptr;
    cudaGetSymbolAddress(&sp, g_scratch);
    float* base  = (float*)sp;
    float* p_h   = base + OFF_H;
    float* p_wp  = base + OFF_WP;
    float* p_q   = base + OFF_Q;
    float* p_k   = base + OFF_K;
    float* p_v   = base + OFF_V;
    float* p_S   = base + OFF_S;
    float* p_m   = base + OFF_M;
    float* p_l   = base + OFF_L;
    float* p_ao  = base + OFF_AO;
    float* p_x2  = base + OFF_X2;
    float* p_h2  = base + OFF_H2;
    float* p_ff  = base + OFF_FF;

    // 1. h = LN1(x)
    ln_kernel<<<M_ROWS, 256>>>(x, g1, beta1, p_h);
    // 2. pack QKV weights
    pack_kernel<<<(C_EMB * C_EMB + 255) / 256, 256>>>(Wq, Wk, Wv, p_wp);
    // 3. q,k,v = h @ Wpack  (scatter into [BH,T,D])
    gemm_kernel<3><<<dim3(1536 / 64, M_ROWS / 128), 256>>>(
        p_h, p_wp, nullptr, M_ROWS, 1536, C_EMB, nullptr, nullptr, p_q, p_k, p_v);
    // 4. S = mask(scale * q k^T)   (lower-triangular tiles only)
    score_kernel<<<dim3(T_SEQ / 64, T_SEQ / 64, BH), 256>>>(p_q, p_k, p_S);
    // 5. per-column (key-axis) softmax stats over query axis
    colstats_kernel<<<dim3(T_SEQ / 256, BH), 256>>>(p_S, p_m, p_l);
    // 6. attention out = P @ V, written as [B,T,C] head-concat
    pv_kernel<<<dim3(T_SEQ / 64, 1, BH), 256>>>(p_S, p_v, p_m, p_l, p_ao);
    // 7. x2 = x + ao @ Wo + bo
    gemm_kernel<1><<<dim3(C_EMB / 64, M_ROWS / 128), 256>>>(
        p_ao, Wo, p_x2, M_ROWS, C_EMB, C_EMB, bo, x, nullptr, nullptr, nullptr);
    // 8. h2 = LN2(x2)
    ln_kernel<<<M_ROWS, 256>>>(p_x2, g2, beta2, p_h2);
    // 9. ff = relu(h2 @ W1 + b1)
    gemm_kernel<2><<<dim3(4 * C_EMB / 64, M_ROWS / 128), 256>>>(
        p_h2, W1, p_ff, M_ROWS, 4 * C_EMB, C_EMB, b1, nullptr, nullptr, nullptr, nullptr);
    // 10. out = x2 + ff @ W2 + b2
    gemm_kernel<1><<<dim3(C_EMB / 64, M_ROWS / 128), 256>>>(
        p_ff, W2, out, M_ROWS, C_EMB, 4 * C_EMB, b2, p_x2, nullptr, nullptr, nullptr);
}

// round 2
// speedup vs baseline: 1.0036x; 1.0036x over previous
#include <cuda_runtime.h>
#include <cstdint>
#include <cstddef>

// Problem constants
#define T_SEQ 2048
#define C_EMB 512
#define NB 4
#define NHD 8
#define HD 64
#define BH (NB*NHD)
#define M_ROWS (NB*T_SEQ)   // 8192

// ---------------- scratch layout (one __device__ symbol, no allocations) ----
constexpr size_t SZ_H   = (size_t)M_ROWS * C_EMB;        // 4M floats
constexpr size_t SZ_WP  = (size_t)C_EMB * 1536;          // packed QKV weights
constexpr size_t SZ_QKV = (size_t)BH * T_SEQ * HD;       // 4M floats each
constexpr size_t SZ_S   = (size_t)BH * T_SEQ * T_SEQ;    // 134M floats (512MB)
constexpr size_t SZ_COL = (size_t)BH * T_SEQ;
constexpr size_t SZ_FF  = (size_t)M_ROWS * 4 * C_EMB;    // 16.8M floats

constexpr size_t OFF_H  = 0;
constexpr size_t OFF_WP = OFF_H  + SZ_H;
constexpr size_t OFF_Q  = OFF_WP + SZ_WP;
constexpr size_t OFF_K  = OFF_Q  + SZ_QKV;
constexpr size_t OFF_V  = OFF_K  + SZ_QKV;
constexpr size_t OFF_S  = OFF_V  + SZ_QKV;
constexpr size_t OFF_M  = OFF_S  + SZ_S;
constexpr size_t OFF_L  = OFF_M  + SZ_COL;
constexpr size_t OFF_AO = OFF_L  + SZ_COL;
constexpr size_t OFF_X2 = OFF_AO + SZ_H;
constexpr size_t OFF_H2 = OFF_X2 + SZ_H;
constexpr size_t OFF_FF = OFF_H2 + SZ_H;
constexpr size_t SZ_TOTAL = OFF_FF + SZ_FF;

__device__ float g_scratch[SZ_TOTAL];

// ---------------- LayerNorm: one block (256 thr) per row of 512 -------------
__global__ __launch_bounds__(256) void ln_kernel(
    const float* __restrict__ x, const float* __restrict__ g,
    const float* __restrict__ be, float* __restrict__ o)
{
    const int row = blockIdx.x;
    const float* xr = x + (size_t)row * C_EMB;
    const int t = threadIdx.x;
    float a = xr[t], b = xr[t + 256];
    float s  = a + b;
    float sq = a * a + b * b;
    #pragma unroll
    for (int off = 16; off; off >>= 1) {
        s  += __shfl_xor_sync(0xffffffffu, s,  off);
        sq += __shfl_xor_sync(0xffffffffu, sq, off);
    }
    __shared__ float sh[16];
    const int w = t >> 5;
    if ((t & 31) == 0) { sh[w] = s; sh[8 + w] = sq; }
    __syncthreads();
    if (t == 0) {
        float S = 0.f, Q = 0.f;
        #pragma unroll
        for (int i = 0; i < 8; i++) { S += sh[i]; Q += sh[8 + i]; }
        sh[0] = S; sh[8] = Q;
    }
    __syncthreads();
    const float mu  = sh[0] * (1.f / 512.f);
    const float var = sh[8] * (1.f / 512.f) - mu * mu;
    const float inv = rsqrtf(var + 1e-5f);
    o[(size_t)row * C_EMB + t]       = (a - mu) * inv * g[t]       + be[t];
    o[(size_t)row * C_EMB + t + 256] = (b - mu) * inv * g[t + 256] + be[t + 256];
}

// ---------------- pack Wq/Wk/Wv [H,C,D] -> Wpack [C, 1536] ------------------
__global__ void pack_kernel(const float* __restrict__ Wq, const float* __restrict__ Wk,
                            const float* __restrict__ Wv, float* __restrict__ wp)
{
    int idx = blockIdx.x * blockDim.x + threadIdx.x;
    if (idx >= C_EMB * C_EMB) return;
    int c = idx / C_EMB;
    int n = idx % C_EMB;       // n = h*64 + d
    int h = n >> 6, d = n & 63;
    size_t src = ((size_t)h * C_EMB + c) * HD + d;
    wp[(size_t)c * 1536 + n]        = Wq[src];
    wp[(size_t)c * 1536 + 512 + n]  = Wk[src];
    wp[(size_t)c * 1536 + 1024 + n] = Wv[src];
}

// ---------------- generic tiled SGEMM: C = A[MxK] @ B[KxN] ------------------
// BM=128, BN=64, BK=16, 256 threads, 8x4 micro-tile.
// MODE 0: plain   MODE 1: +bias[n]+res   MODE 2: relu(+bias)   MODE 3: QKV scatter
template<int MODE>
__global__ __launch_bounds__(256) void gemm_kernel(
    const float* __restrict__ A, const float* __restrict__ B, float* __restrict__ C,
    int M, int N, int K,
    const float* __restrict__ bias, const float* __restrict__ res,
    float* __restrict__ Cq, float* __restrict__ Ck, float* __restrict__ Cv)
{
    __shared__ float As[128][17];
    __shared__ __align__(16) float Bs[16][68];
    const int tid = threadIdx.x;
    const int m0 = blockIdx.y * 128;
    const int n0 = blockIdx.x * 64;
    const int ty = tid >> 4;        // 0..15
    const int tx = tid & 15;        // 0..15
    const int arow_base = tid >> 2; // 0..63
    const int acol = (tid & 3) << 2;
    const int brow = tid >> 4;
    const int bcol = (tid & 15) << 2;

    float acc[8][4];
    #pragma unroll
    for (int i = 0; i < 8; i++)
        #pragma unroll
        for (int j = 0; j < 4; j++) acc[i][j] = 0.f;

    for (int k0 = 0; k0 < K; k0 += 16) {
        #pragma unroll
        for (int p = 0; p < 2; ++p) {
            int ar = arow_base + p * 64;
            float4 av = *reinterpret_cast<const float4*>(A + (size_t)(m0 + ar) * K + k0 + acol);
            As[ar][acol + 0] = av.x; As[ar][acol + 1] = av.y;
            As[ar][acol + 2] = av.z; As[ar][acol + 3] = av.w;
        }
        {
            float4 bv = *reinterpret_cast<const float4*>(B + (size_t)(k0 + brow) * N + n0 + bcol);
            Bs[brow][bcol + 0] = bv.x; Bs[brow][bcol + 1] = bv.y;
            Bs[brow][bcol + 2] = bv.z; Bs[brow][bcol + 3] = bv.w;
        }
        __syncthreads();
        #pragma unroll
        for (int k = 0; k < 16; k++) {
            float a[8];
            #pragma unroll
            for (int i = 0; i < 8; i++) a[i] = As[ty * 8 + i][k];
            float4 b4 = *reinterpret_cast<const float4*>(&Bs[k][tx * 4]);
            float b[4] = {b4.x, b4.y, b4.z, b4.w};
            #pragma unroll
            for (int i = 0; i < 8; i++)
                #pragma unroll
                for (int j = 0; j < 4; j++)
                    acc[i][j] = fmaf(a[i], b[j], acc[i][j]);
        }
        __syncthreads();
    }

    #pragma unroll
    for (int i = 0; i < 8; i++) {
        const int m = m0 + ty * 8 + i;
        #pragma unroll
        for (int j = 0; j < 4; j++) {
            const int n = n0 + tx * 4 + j;
            float v = acc[i][j];
            if (MODE == 0) {
                C[(size_t)m * N + n] = v;
            } else if (MODE == 1) {
                C[(size_t)m * N + n] = v + bias[n] + res[(size_t)m * N + n];
            } else if (MODE == 2) {
                C[(size_t)m * N + n] = fmaxf(v + bias[n], 0.f);
            } else { // QKV scatter: n -> (which, h, d), m -> (b, t); dst layout [BH,T,D]
                int which = n >> 9, nn = n & 511;
                int h = nn >> 6, d = nn & 63;
                int b = m >> 11, t = m & 2047;
                float* dst = (which == 0) ? Cq : ((which == 1) ? Ck : Cv);
                dst[(((size_t)(b * NHD + h)) * T_SEQ + t) * HD + d] = v;
            }
        }
    }
}

// ---------------- attention scores: S[t,s] = scale * q.k, causal-masked -----
__global__ __launch_bounds__(256) void score_kernel(
    const float* __restrict__ q, const float* __restrict__ kmat, float* __restrict__ S)
{
    const int tt = blockIdx.x;   // t tile
    const int st = blockIdx.y;   // s tile
    const int bh = blockIdx.z;
    if (st > tt) return;         // strictly-upper tiles never written/read

    __shared__ float Qs[64][65];
    __shared__ float Ks[64][65];
    const int tid = threadIdx.x;
    const float* qb = q    + ((size_t)bh * T_SEQ + tt * 64) * HD;
    const float* kb = kmat + ((size_t)bh * T_SEQ + st * 64) * HD;
    const int r4 = tid >> 6, c = tid & 63;
    #pragma unroll
    for (int p = 0; p < 16; ++p) {
        int row = p * 4 + r4;
        Qs[row][c] = qb[row * HD + c];
        Ks[row][c] = kb[row * HD + c];
    }
    __syncthreads();

    const int ty = tid >> 4, tx = tid & 15;
    float acc[4][4];
    #pragma unroll
    for (int i = 0; i < 4; i++)
        #pragma unroll
        for (int j = 0; j < 4; j++) acc[i][j] = 0.f;

    #pragma unroll 16
    for (int k = 0; k < 64; k++) {
        float a[4], b[4];
        #pragma unroll
        for (int i = 0; i < 4; i++) a[i] = Qs[ty * 4 + i][k];
        #pragma unroll
        for (int j = 0; j < 4; j++) b[j] = Ks[tx * 4 + j][k];
        #pragma unroll
        for (int i = 0; i < 4; i++)
            #pragma unroll
            for (int j = 0; j < 4; j++)
                acc[i][j] = fmaf(a[i], b[j], acc[i][j]);
    }

    const float scale = 0.04419417382415922f;  // 512^-0.5
    float* Sb = S + (size_t)bh * T_SEQ * T_SEQ;
    #pragma unroll
    for (int i = 0; i < 4; i++) {
        const int t = tt * 64 + ty * 4 + i;
        #pragma unroll
        for (int j = 0; j < 4; j++) {
            const int s = st * 64 + tx * 4 + j;
            float v = acc[i][j] * scale;
            if (s > t) v = -1e30f;               // mask (finite: avoids inf-inf NaN)
            Sb[(size_t)t * T_SEQ + s] = v;
        }
    }
}

// ---------------- per-KEY-column softmax stats (online max/sum over t) ------
__global__ __launch_bounds__(256) void colstats_kernel(
    const float* __restrict__ S, float* __restrict__ mcol, float* __restrict__ lcol)
{
    const int bh = blockIdx.y;
    const int s  = blockIdx.x * 256 + threadIdx.x;
    const float* Sb = S + (size_t)bh * T_SEQ * T_SEQ;
    const int t0 = s & ~63;      // first written row for this column
    float mx = -3.4e38f, sum = 0.f;
    for (int t = t0; t < T_SEQ; ++t) {
        float v = Sb[(size_t)t * T_SEQ + s];
        if (v > mx) { sum = sum * __expf(mx - v) + 1.f; mx = v; }
        else        { sum += __expf(v - mx); }
    }
    mcol[(size_t)bh * T_SEQ + s] = mx;
    lcol[(size_t)bh * T_SEQ + s] = 1.f / sum;
}

// ---------------- out = P @ V, P = exp(S - m[s]) * linv[s], s <= t ----------
__global__ __launch_bounds__(256) void pv_kernel(
    const float* __restrict__ S, const float* __restrict__ V,
    const float* __restrict__ mcol, const float* __restrict__ lcol,
    float* __restrict__ ao)
{
    const int tt = blockIdx.x;
    const int bh = blockIdx.z;
    __shared__ float Ps[64][65];                   // [s_local][t_local]
    __shared__ __align__(16) float Vs[64][68];     // [s_local][d]
    const int tid = threadIdx.x;
    const float* Sb = S    + (size_t)bh * T_SEQ * T_SEQ;
    const float* mb = mcol + (size_t)bh * T_SEQ;
    const float* lb = lcol + (size_t)bh * T_SEQ;
    const int ty = tid >> 4, tx = tid & 15;
    const int r4 = tid >> 6, c = tid & 63;

    float acc[4][4];
    #pragma unroll
    for (int i = 0; i < 4; i++)
        #pragma unroll
        for (int j = 0; j < 4; j++) acc[i][j] = 0.f;

    for (int st = 0; st <= tt; ++st) {
        const int s = st * 64 + c;
        const float ms = mb[s];
        const float ls = lb[s];
        #pragma unroll
        for (int p = 0; p < 16; ++p) {
            const int row = p * 4 + r4;
            float z = Sb[(size_t)(tt * 64 + row) * T_SEQ + s];
            Ps[c][row] = __expf(z - ms) * ls;
            Vs[row][c] = V[((size_t)bh * T_SEQ + st * 64 + row) * HD + c];
        }
        __syncthreads();
        #pragma unroll 16
        for (int k = 0; k < 64; k++) {
            float a[4];
            #pragma unroll
            for (int i = 0; i < 4; i++) a[i] = Ps[k][ty * 4 + i];
            float4 b4 = *reinterpret_cast<const float4*>(&Vs[k][tx * 4]);
            float b[4] = {b4.x, b4.y, b4.z, b4.w};
            #pragma unroll
            for (int i = 0; i < 4; i++)
                #pragma unroll
                for (int j = 0; j < 4; j++)
                    acc[i][j] = fmaf(a[i], b[j], acc[i][j]);
        }
        __syncthreads();
    }

    const int b = bh >> 3, h = bh & 7;
    #pragma unroll
    for (int i = 0; i < 4; i++) {
        const int t = tt * 64 + ty * 4 + i;
        #pragma unroll
        for (int j = 0; j < 4; j++) {
            ao[(size_t)(b * T_SEQ + t) * C_EMB + h * HD + tx * 4 + j] = acc[i][j];
        }
    }
}

// ---------------- launcher ---------------------------------------------------
extern "C" void kernel_launch(void* const* d_in, const int* in_sizes, int n_in,
                              void* d_out, int out_size)
{
    const float* x     = (const float*)d_in[0];
    const float* Wq    = (const float*)d_in[1];
    const float* Wk    = (const float*)d_in[2];
    const float* Wv    = (const float*)d_in[3];
    const float* Wo    = (const float*)d_in[4];
    const float* bo    = (const float*)d_in[5];
    const float* W1    = (const float*)d_in[6];
    const float* b1    = (const float*)d_in[7];
    const float* W2    = (const float*)d_in[8];
    const float* b2    = (const float*)d_in[9];
    const float* g1    = (const float*)d_in[10];
    const float* beta1 = (const float*)d_in[11];
    const float* g2    = (const float*)d_in[12];
    const float* beta2 = (const float*)d_in[13];
    float* out = (float*)d_out;

    void* sp = nullptr;
    cudaGetSymbolAddress(&sp, g_scratch);
    float* base  = (float*)sp;
    float* p_h   = base + OFF_H;
    float* p_wp  = base + OFF_WP;
    float* p_q   = base + OFF_Q;
    float* p_k   = base + OFF_K;
    float* p_v   = base + OFF_V;
    float* p_S   = base + OFF_S;
    float* p_m   = base + OFF_M;
    float* p_l   = base + OFF_L;
    float* p_ao  = base + OFF_AO;
    float* p_x2  = base + OFF_X2;
    float* p_h2  = base + OFF_H2;
    float* p_ff  = base + OFF_FF;

    // 1. h = LN1(x)
    ln_kernel<<<M_ROWS, 256>>>(x, g1, beta1, p_h);
    // 2. pack QKV weights
    pack_kernel<<<(C_EMB * C_EMB + 255) / 256, 256>>>(Wq, Wk, Wv, p_wp);
    // 3. q,k,v = h @ Wpack  (scatter into [BH,T,D])
    gemm_kernel<3><<<dim3(1536 / 64, M_ROWS / 128), 256>>>(
        p_h, p_wp, nullptr, M_ROWS, 1536, C_EMB, nullptr, nullptr, p_q, p_k, p_v);
    // 4. S = mask(scale * q k^T)   (lower-triangular tiles only)
    score_kernel<<<dim3(T_SEQ / 64, T_SEQ / 64, BH), 256>>>(p_q, p_k, p_S);
    // 5. per-column (key-axis) softmax stats over query axis
    colstats_kernel<<<dim3(T_SEQ / 256, BH), 256>>>(p_S, p_m, p_l);
    // 6. attention out = P @ V, written as [B,T,C] head-concat
    pv_kernel<<<dim3(T_SEQ / 64, 1, BH), 256>>>(p_S, p_v, p_m, p_l, p_ao);
    // 7. x2 = x + ao @ Wo + bo
    gemm_kernel<1><<<dim3(C_EMB / 64, M_ROWS / 128), 256>>>(
        p_ao, Wo, p_x2, M_ROWS, C_EMB, C_EMB, bo, x, nullptr, nullptr, nullptr);
    // 8. h2 = LN2(x2)
    ln_kernel<<<M_ROWS, 256>>>(p_x2, g2, beta2, p_h2);
    // 9. ff = relu(h2 @ W1 + b1)
    gemm_kernel<2><<<dim3(4 * C_EMB / 64, M_ROWS / 128), 256>>>(
        p_h2, W1, p_ff, M_ROWS, 4 * C_EMB, C_EMB, b1, nullptr, nullptr, nullptr, nullptr);
    // 10. out = x2 + ff @ W2 + b2
    gemm_kernel<1><<<dim3(C_EMB / 64, M_ROWS / 128), 256>>>(
        p_ff, W2, out, M_ROWS, C_EMB, 4 * C_EMB, b2, p_x2, nullptr, nullptr, nullptr);
}

// round 4
// speedup vs baseline: 2.9333x; 2.9229x over previous
#include <cuda_runtime.h>
#include <cuda_fp16.h>
#include <cstdint>
#include <cstddef>

#define TS 2048
#define CE 512
#define DINL __device__ __forceinline__

// ---------------- scratch (bytes) ----------------
constexpr size_t B_ROWC = (size_t)8192 * 512 * 2;
constexpr size_t B_FF   = (size_t)8192 * 2048 * 2;
constexpr size_t B_QKV  = (size_t)32 * 2048 * 64 * 2;
constexpr size_t B_S    = (size_t)32 * 2048 * 2048 * 2;
constexpr size_t B_COL  = (size_t)32 * 2048 * 4;
constexpr size_t O_H    = 0;
constexpr size_t O_H2   = O_H   + B_ROWC;
constexpr size_t O_AO   = O_H2  + B_ROWC;
constexpr size_t O_FF   = O_AO  + B_ROWC;
constexpr size_t O_Q    = O_FF  + B_FF;
constexpr size_t O_K    = O_Q   + B_QKV;
constexpr size_t O_VT   = O_K   + B_QKV;
constexpr size_t O_WQKV = O_VT  + B_QKV;
constexpr size_t O_WOT  = O_WQKV + (size_t)1536*512*2;
constexpr size_t O_W1T  = O_WOT  + (size_t)512*512*2;
constexpr size_t O_W2T  = O_W1T  + (size_t)2048*512*2;
constexpr size_t O_S    = O_W2T  + (size_t)512*2048*2;
constexpr size_t O_M    = O_S   + B_S;
constexpr size_t O_L    = O_M   + B_COL;
constexpr size_t O_X2   = O_L   + B_COL;
constexpr size_t SZ_ALL = O_X2  + (size_t)8192*512*4;

__device__ __align__(128) unsigned char g_s[SZ_ALL];

// ---------------- helpers ----------------
DINL uint32_t smem_u32(const void* p) {
    uint32_t a;
    asm("{ .reg .u64 t; cvta.to.shared.u64 t, %1; cvt.u32.u64 %0, t; }" : "=r"(a) : "l"(p));
    return a;
}
DINL uint32_t sw128(uint32_t off) { return off ^ ((off >> 3) & 0x70); }

DINL void ldsm4(uint32_t* r, uint32_t a) {
    asm volatile("ldmatrix.sync.aligned.m8n8.x4.shared.b16 {%0,%1,%2,%3}, [%4];"
        : "=r"(r[0]), "=r"(r[1]), "=r"(r[2]), "=r"(r[3]) : "r"(a));
}
DINL void mma16816(float* d, const uint32_t* a, const uint32_t* b) {
    asm volatile("mma.sync.aligned.m16n8k16.row.col.f32.f16.f16.f32 "
        "{%0,%1,%2,%3},{%4,%5,%6,%7},{%8,%9},{%0,%1,%2,%3};"
        : "+f"(d[0]), "+f"(d[1]), "+f"(d[2]), "+f"(d[3])
        : "r"(a[0]), "r"(a[1]), "r"(a[2]), "r"(a[3]), "r"(b[0]), "r"(b[1]));
}
DINL uint32_t pack2(float a, float b) {
    union { __half2 h; uint32_t u; } cv;
    cv.h = __floats2half2_rn(a, b);
    return cv.u;
}
// tiles: rows of 64 halves (128B), SW128-swizzled in SMEM; 256 threads
template<int NR>
DINL void ld_tile(const __half* __restrict__ g, int ldh, char* __restrict__ smp, int tid) {
    #pragma unroll
    for (int p = 0; p < NR / 32; p++) {
        int u = tid + (p << 8), r = u >> 3, cc = u & 7;
        *reinterpret_cast<uint4*>(smp + sw128((uint32_t)(r << 7) + (cc << 4))) =
            *reinterpret_cast<const uint4*>(g + (size_t)r * ldh + (cc << 3));
    }
}
template<int NR>
DINL void ldg_tile(const __half* __restrict__ g, int ldh, uint4* v, int tid) {
    #pragma unroll
    for (int p = 0; p < NR / 32; p++) {
        int u = tid + (p << 8), r = u >> 3, cc = u & 7;
        v[p] = *reinterpret_cast<const uint4*>(g + (size_t)r * ldh + (cc << 3));
    }
}
template<int NR>
DINL void sts_tile(char* __restrict__ smp, const uint4* v, int tid) {
    #pragma unroll
    for (int p = 0; p < NR / 32; p++) {
        int u = tid + (p << 8), r = u >> 3, cc = u & 7;
        *reinterpret_cast<uint4*>(smp + sw128((uint32_t)(r << 7) + (cc << 4))) = v[p];
    }
}
// A fragments: 4 m-tiles of 16 rows starting at m0
DINL void ldA(uint32_t buf, int lane, int m0, int ks, uint32_t a[4][4]) {
    int row = m0 + (lane & 15);
    uint32_t koff = (uint32_t)(ks << 5) + ((lane & 16) ? 16u : 0u);
    #pragma unroll
    for (int mt = 0; mt < 4; mt++)
        ldsm4(a[mt], buf + sw128((uint32_t)((row + mt * 16) << 7) + koff));
}
// B fragments: one x4 ldmatrix covers 16 n-rows (two 16x8 n-tiles)
DINL void ldB16(uint32_t buf, int lane, int n0, int ks, uint32_t b[4]) {
    int row = n0 + (lane & 7) + ((lane & 16) >> 1);
    uint32_t koff = (uint32_t)(ks << 5) + ((lane & 8) << 1);
    ldsm4(b, buf + sw128((uint32_t)(row << 7) + koff));
}
// 64-k chunk of 128x128 mma (warp tile 64x32)
DINL void mma_chunk(uint32_t abuf, uint32_t bbuf, int lane, int wm, int wn, float acc[4][4][4]) {
    #pragma unroll
    for (int ks = 0; ks < 4; ks++) {
        uint32_t a[4][4], b[2][4];
        ldA(abuf, lane, wm * 64, ks, a);
        ldB16(bbuf, lane, wn * 32, ks, b[0]);
        ldB16(bbuf, lane, wn * 32 + 16, ks, b[1]);
        #pragma unroll
        for (int mt = 0; mt < 4; mt++)
            #pragma unroll
            for (int nt = 0; nt < 4; nt++)
                mma16816(acc[mt][nt], a[mt], &b[nt >> 1][(nt & 1) * 2]);
    }
}

// ---------------- LayerNorm fp32 -> fp16 ----------------
__global__ __launch_bounds__(256) void ln_h(
    const float* __restrict__ x, const float* __restrict__ g,
    const float* __restrict__ be, __half* __restrict__ o)
{
    const int row = blockIdx.x, t = threadIdx.x;
    const float* xr = x + (size_t)row * CE;
    float2 ab = *reinterpret_cast<const float2*>(xr + 2 * t);
    float s = ab.x + ab.y, sq = ab.x * ab.x + ab.y * ab.y;
    #pragma unroll
    for (int off = 16; off; off >>= 1) {
        s  += __shfl_xor_sync(~0u, s, off);
        sq += __shfl_xor_sync(~0u, sq, off);
    }
    __shared__ float sh[16];
    if ((t & 31) == 0) { sh[t >> 5] = s; sh[8 + (t >> 5)] = sq; }
    __syncthreads();
    if (t == 0) {
        float S = 0, Q = 0;
        #pragma unroll
        for (int i = 0; i < 8; i++) { S += sh[i]; Q += sh[8 + i]; }
        sh[0] = S; sh[8] = Q;
    }
    __syncthreads();
    float mu = sh[0] * (1.f / 512), var = sh[8] * (1.f / 512) - mu * mu;
    float inv = rsqrtf(var + 1e-5f);
    float o0 = (ab.x - mu) * inv * g[2 * t] + be[2 * t];
    float o1 = (ab.y - mu) * inv * g[2 * t + 1] + be[2 * t + 1];
    *reinterpret_cast<__half2*>(o + (size_t)row * CE + 2 * t) = __floats2half2_rn(o0, o1);
}

// ---------------- weight prep ----------------
__global__ void packqkv(const float* __restrict__ Wq, const float* __restrict__ Wk,
                        const float* __restrict__ Wv, __half* __restrict__ wt)
{
    __shared__ float tl[32][33];
    int c0 = blockIdx.x << 5, d0 = blockIdx.y << 5, z = blockIdx.z;
    int which = z >> 3, h = z & 7;
    const float* W = which == 0 ? Wq : (which == 1 ? Wk : Wv);
    float sc = which == 0 ? 0.04419417382415922f : 1.f;
    tl[threadIdx.y][threadIdx.x] =
        W[((size_t)h * 512 + c0 + threadIdx.y) * 64 + d0 + threadIdx.x] * sc;
    __syncthreads();
    wt[((size_t)(which * 512 + h * 64 + d0 + threadIdx.y)) * 512 + c0 + threadIdx.x] =
        __float2half(tl[threadIdx.x][threadIdx.y]);
}
__global__ void tr_kernel(const float* __restrict__ in, __half* __restrict__ out, int K, int N)
{
    __shared__ float tl[32][33];
    int n0 = blockIdx.x << 5, k0 = blockIdx.y << 5;
    tl[threadIdx.y][threadIdx.x] = in[(size_t)(k0 + threadIdx.y) * N + n0 + threadIdx.x];
    __syncthreads();
    out[(size_t)(n0 + threadIdx.y) * K + k0 + threadIdx.x] = __float2half(tl[threadIdx.x][threadIdx.y]);
}

// ---------------- GEMM: 128x128 tile of A[M,K] @ Bt[N,K]^T ----------------
// MODE 0: QKV scatter   1: +bias+res -> fp32   2: relu(+bias) -> fp16 (ld 2048)
template<int MODE>
__global__ __launch_bounds__(256) void gemm_mma(
    const __half* __restrict__ A, const __half* __restrict__ B, int K,
    const float* __restrict__ bias, const float* __restrict__ res,
    float* __restrict__ outf, __half* __restrict__ outh,
    __half* __restrict__ oq, __half* __restrict__ ok2, __half* __restrict__ ov)
{
    extern __shared__ __align__(1024) char sm[];
    const uint32_t sb = smem_u32(sm);
    const int tid = threadIdx.x, lane = tid & 31, w = tid >> 5;
    const int wm = w & 1, wn = w >> 1;
    const int m0 = blockIdx.y << 7, n0 = blockIdx.x << 7;
    const __half* Ab = A + (size_t)m0 * K;
    const __half* Bb = B + (size_t)n0 * K;
    float acc[4][4][4];
    #pragma unroll
    for (int i = 0; i < 4; i++)
        #pragma unroll
        for (int j = 0; j < 4; j++)
            #pragma unroll
            for (int e = 0; e < 4; e++) acc[i][j][e] = 0.f;

    ld_tile<128>(Ab, K, sm, tid);
    ld_tile<128>(Bb, K, sm + 32768, tid);
    __syncthreads();
    const int nc = K >> 6;
    for (int c = 0; c < nc; c++) {
        uint4 va[4], vb[4];
        if (c + 1 < nc) {
            ldg_tile<128>(Ab + ((c + 1) << 6), K, va, tid);
            ldg_tile<128>(Bb + ((c + 1) << 6), K, vb, tid);
        }
        mma_chunk(sb + ((uint32_t)(c & 1) << 14), sb + 32768 + ((uint32_t)(c & 1) << 14),
                  lane, wm, wn, acc);
        __syncthreads();
        if (c + 1 < nc) {
            sts_tile<128>(sm + (((c + 1) & 1) << 14), va, tid);
            sts_tile<128>(sm + 32768 + (((c + 1) & 1) << 14), vb, tid);
        }
        __syncthreads();
    }
    const int gm = lane >> 2, gn2 = (lane & 3) << 1;
    #pragma unroll
    for (int mt = 0; mt < 4; mt++) {
        #pragma unroll
        for (int nt = 0; nt < 4; nt++) {
            #pragma unroll
            for (int hf = 0; hf < 2; hf++) {
                const int m = m0 + wm * 64 + mt * 16 + gm + hf * 8;
                const int n = n0 + wn * 32 + nt * 8 + gn2;
                float v0 = acc[mt][nt][hf * 2 + 0], v1 = acc[mt][nt][hf * 2 + 1];
                if (MODE == 1) {
                    size_t ri = (size_t)m * 512 + n;
                    float2 o = { v0 + bias[n] + res[ri], v1 + bias[n + 1] + res[ri + 1] };
                    *reinterpret_cast<float2*>(outf + ri) = o;
                } else if (MODE == 2) {
                    *reinterpret_cast<uint32_t*>(outh + (size_t)m * 2048 + n) =
                        pack2(fmaxf(v0 + bias[n], 0.f), fmaxf(v1 + bias[n + 1], 0.f));
                } else {
                    int which = n0 >> 9;
                    int hh = (n & 511) >> 6, d = n & 63;
                    int b = m >> 11, t2 = m & 2047;
                    int bh = (b << 3) + hh;
                    if (which < 2) {
                        __half* dst = which == 0 ? oq : ok2;
                        *reinterpret_cast<uint32_t*>(dst + ((size_t)bh * 2048 + t2) * 64 + d) =
                            pack2(v0, v1);
                    } else {
                        ov[((size_t)bh * 64 + d) * 2048 + t2]     = __float2half(v0);
                        ov[((size_t)bh * 64 + d + 1) * 2048 + t2] = __float2half(v1);
                    }
                }
            }
        }
    }
}

// ---------------- scores: per (bh, 128-row t-tile), loop s-tiles ----------
__global__ __launch_bounds__(256) void score_mma(
    const __half* __restrict__ q, const __half* __restrict__ k, __half* __restrict__ S)
{
    extern __shared__ __align__(1024) char sm[];
    const uint32_t sb = smem_u32(sm);
    const int tid = threadIdx.x, lane = tid & 31, w = tid >> 5;
    const int wm = w & 1, wn = w >> 1;
    const int tt = (int)gridDim.x - 1 - (int)blockIdx.x, bh = blockIdx.y;
    const __half* qb = q + ((size_t)bh * TS + (size_t)tt * 128) * 64;
    const __half* kb = k + (size_t)bh * TS * 64;
    __half* Sb = S + (size_t)bh * TS * TS;

    ld_tile<128>(qb, 64, sm, tid);
    ld_tile<128>(kb, 64, sm + 16384, tid);
    __syncthreads();
    const int gm = lane >> 2, gn2 = (lane & 3) << 1;
    for (int st = 0; st <= tt; st++) {
        uint4 vk[4];
        if (st < tt) ldg_tile<128>(kb + (size_t)(st + 1) * 128 * 64, 64, vk, tid);
        float acc[4][4][4];
        #pragma unroll
        for (int i = 0; i < 4; i++)
            #pragma unroll
            for (int j = 0; j < 4; j++)
                #pragma unroll
                for (int e = 0; e < 4; e++) acc[i][j][e] = 0.f;
        mma_chunk(sb, sb + 16384 + ((uint32_t)(st & 1) << 14), lane, wm, wn, acc);
        #pragma unroll
        for (int mt = 0; mt < 4; mt++) {
            #pragma unroll
            for (int nt = 0; nt < 4; nt++) {
                #pragma unroll
                for (int hf = 0; hf < 2; hf++) {
                    const int t2 = tt * 128 + wm * 64 + mt * 16 + gm + hf * 8;
                    const int s  = st * 128 + wn * 32 + nt * 8 + gn2;
                    float v0 = acc[mt][nt][hf * 2 + 0], v1 = acc[mt][nt][hf * 2 + 1];
                    if (st == tt) {
                        if (s > t2)     v0 = -30000.f;
                        if (s + 1 > t2) v1 = -30000.f;
                    }
                    *reinterpret_cast<uint32_t*>(Sb + (size_t)t2 * TS + s) = pack2(v0, v1);
                }
            }
        }
        __syncthreads();
        if (st < tt) sts_tile<128>(sm + 16384 + (((st + 1) & 1) << 14), vk, tid);
        __syncthreads();
    }
}

// ---------------- column softmax stats ----------------
__global__ __launch_bounds__(256) void colstats(
    const __half* __restrict__ S, float* __restrict__ mc, float* __restrict__ lc)
{
    const int bh = blockIdx.y, s = blockIdx.x * 256 + threadIdx.x;
    const __half* Sb = S + (size_t)bh * TS * TS;
    float mx = -3.4e38f, sum = 0.f;
    for (int t = s & ~127; t < TS; t++) {
        float v = __half2float(Sb[(size_t)t * TS + s]);
        if (v > mx) { sum = sum * __expf(mx - v) + 1.f; mx = v; }
        else sum += __expf(v - mx);
    }
    mc[(size_t)bh * TS + s] = mx;
    lc[(size_t)bh * TS + s] = 1.f / sum;
}

// ---------------- PV: out[128t,64d] = P @ Vt^T ----------------
__global__ __launch_bounds__(256) void pv_mma(
    const __half* __restrict__ S, const __half* __restrict__ Vt,
    const float* __restrict__ mc, const float* __restrict__ lc,
    __half* __restrict__ ao)
{
    extern __shared__ __align__(1024) char sm[];
    float* smM = reinterpret_cast<float*>(sm);
    float* smL = reinterpret_cast<float*>(sm + 256);
    char* Pt = sm + 1024;
    char* Vtile = sm + 1024 + 16384;
    const uint32_t ptb = smem_u32(Pt), vtb = smem_u32(Vtile);
    const int tid = threadIdx.x, lane = tid & 31, w = tid >> 5;
    const int wm = w & 1, wn = w >> 1;
    const int tt = (int)gridDim.x - 1 - (int)blockIdx.x, bh = blockIdx.y;
    const __half* Sb = S + ((size_t)bh * TS + (size_t)tt * 128) * TS;
    const __half* Vb = Vt + (size_t)bh * 64 * TS;
    const float* mb = mc + (size_t)bh * TS;
    const float* lb = lc + (size_t)bh * TS;

    float acc[4][2][4];
    #pragma unroll
    for (int i = 0; i < 4; i++)
        #pragma unroll
        for (int j = 0; j < 2; j++)
            #pragma unroll
            for (int e = 0; e < 4; e++) acc[i][j][e] = 0.f;

    const int nch = 2 * (tt + 1);
    for (int c = 0; c < nch; c++) {
        __syncthreads();
        if (tid < 64) { smM[tid] = mb[c * 64 + tid]; smL[tid] = lb[c * 64 + tid]; }
        ld_tile<64>(Vb + c * 64, TS, Vtile, tid);
        __syncthreads();
        #pragma unroll
        for (int p = 0; p < 4; p++) {
            int u = tid + (p << 8), r = u >> 3, cc = u & 7;
            uint4 sv = *reinterpret_cast<const uint4*>(Sb + (size_t)r * TS + c * 64 + (cc << 3));
            const __half2* hp = reinterpret_cast<const __half2*>(&sv);
            uint32_t pk[4];
            #pragma unroll
            for (int j = 0; j < 4; j++) {
                float2 f = __half22float2(hp[j]);
                int s0 = (cc << 3) + 2 * j;
                pk[j] = pack2(__expf(f.x - smM[s0]) * smL[s0],
                              __expf(f.y - smM[s0 + 1]) * smL[s0 + 1]);
            }
            *reinterpret_cast<uint4*>(Pt + sw128((uint32_t)(r << 7) + (cc << 4))) =
                make_uint4(pk[0], pk[1], pk[2], pk[3]);
        }
        __syncthreads();
        #pragma unroll
        for (int ks = 0; ks < 4; ks++) {
            uint32_t a[4][4], b[4];
            ldA(ptb, lane, wm * 64, ks, a);
            ldB16(vtb, lane, wn * 16, ks, b);
            #pragma unroll
            for (int mt = 0; mt < 4; mt++) {
                mma16816(acc[mt][0], a[mt], &b[0]);
                mma16816(acc[mt][1], a[mt], &b[2]);
            }
        }
    }
    const int gm = lane >> 2, gn2 = (lane & 3) << 1;
    #pragma unroll
    for (int mt = 0; mt < 4; mt++) {
        #pragma unroll
        for (int nt = 0; nt < 2; nt++) {
            #pragma unroll
            for (int hf = 0; hf < 2; hf++) {
                const int t2 = tt * 128 + wm * 64 + mt * 16 + gm + hf * 8;
                const int n = wn * 16 + nt * 8 + gn2;
                *reinterpret_cast<uint32_t*>(
                    ao + ((size_t)(bh >> 3) * TS + t2) * 512 + (bh & 7) * 64 + n) =
                    pack2(acc[mt][nt][hf * 2 + 0], acc[mt][nt][hf * 2 + 1]);
            }
        }
    }
}

// ---------------- launcher ----------------
extern "C" void kernel_launch(void* const* d_in, const int* in_sizes, int n_in,
                              void* d_out, int out_size)
{
    const float* x  = (const float*)d_in[0];
    const float* Wq = (const float*)d_in[1];
    const float* Wk = (const float*)d_in[2];
    const float* Wv = (const float*)d_in[3];
    const float* Wo = (const float*)d_in[4];
    const float* bo = (const float*)d_in[5];
    const float* W1 = (const float*)d_in[6];
    const float* b1 = (const float*)d_in[7];
    const float* W2 = (const float*)d_in[8];
    const float* b2 = (const float*)d_in[9];
    const float* g1 = (const float*)d_in[10];
    const float* be1= (const float*)d_in[11];
    const float* g2 = (const float*)d_in[12];
    const float* be2= (const float*)d_in[13];
    float* out = (float*)d_out;

    void* sp = nullptr;
    cudaGetSymbolAddress(&sp, g_s);
    unsigned char* b = (unsigned char*)sp;
    __half* p_h   = (__half*)(b + O_H);
    __half* p_h2  = (__half*)(b + O_H2);
    __half* p_ao  = (__half*)(b + O_AO);
    __half* p_ff  = (__half*)(b + O_FF);
    __half* p_q   = (__half*)(b + O_Q);
    __half* p_k   = (__half*)(b + O_K);
    __half* p_vt  = (__half*)(b + O_VT);
    __half* p_wqkv= (__half*)(b + O_WQKV);
    __half* p_wot = (__half*)(b + O_WOT);
    __half* p_w1t = (__half*)(b + O_W1T);
    __half* p_w2t = (__half*)(b + O_W2T);
    __half* p_S   = (__half*)(b + O_S);
    float*  p_m   = (float*)(b + O_M);
    float*  p_l   = (float*)(b + O_L);
    float*  p_x2  = (float*)(b + O_X2);

    cudaFuncSetAttribute(gemm_mma<0>, cudaFuncAttributeMaxDynamicSharedMemorySize, 65536);
    cudaFuncSetAttribute(gemm_mma<1>, cudaFuncAttributeMaxDynamicSharedMemorySize, 65536);
    cudaFuncSetAttribute(gemm_mma<2>, cudaFuncAttributeMaxDynamicSharedMemorySize, 65536);
    cudaFuncSetAttribute(score_mma,   cudaFuncAttributeMaxDynamicSharedMemorySize, 49152);
    cudaFuncSetAttribute(pv_mma,      cudaFuncAttributeMaxDynamicSharedMemorySize, 25600);

    dim3 b32(32, 32);
    ln_h<<<8192, 256>>>(x, g1, be1, p_h);
    packqkv<<<dim3(16, 2, 24), b32>>>(Wq, Wk, Wv, p_wqkv);
    tr_kernel<<<dim3(16, 16), b32>>>(Wo, p_wot, 512, 512);
    tr_kernel<<<dim3(64, 16), b32>>>(W1, p_w1t, 512, 2048);
    tr_kernel<<<dim3(16, 64), b32>>>(W2, p_w2t, 2048, 512);
    gemm_mma<0><<<dim3(12, 64), 256, 65536>>>(p_h, p_wqkv, 512, nullptr, nullptr,
                                              nullptr, nullptr, p_q, p_k, p_vt);
    score_mma<<<dim3(16, 32), 256, 49152>>>(p_q, p_k, p_S);
    colstats<<<dim3(8, 32), 256>>>(p_S, p_m, p_l);
    pv_mma<<<dim3(16, 32), 256, 25600>>>(p_S, p_vt, p_m, p_l, p_ao);
    gemm_mma<1><<<dim3(4, 64), 256, 65536>>>(p_ao, p_wot, 512, bo, x,
                                             p_x2, nullptr, nullptr, nullptr, nullptr);
    ln_h<<<8192, 256>>>(p_x2, g2, be2, p_h2);
    gemm_mma<2><<<dim3(16, 64), 256, 65536>>>(p_h2, p_w1t, 512, b1, nullptr,
                                              nullptr, p_ff, nullptr, nullptr, nullptr);
    gemm_mma<1><<<dim3(4, 64), 256, 65536>>>(p_ff, p_w2t, 2048, b2, p_x2,
                                             out, nullptr, nullptr, nullptr, nullptr);
}

// round 5
// speedup vs baseline: 4.3459x; 1.4816x over previous
#include <cuda_runtime.h>
#include <cuda_fp16.h>
#include <cstdint>
#include <cstddef>

#define TS 2048
#define CE 512
#define DINL __device__ __forceinline__

// ---------------- scratch (bytes) ----------------
constexpr size_t B_ROWC = (size_t)8192 * 512 * 2;
constexpr size_t B_FF   = (size_t)8192 * 2048 * 2;
constexpr size_t B_QKV  = (size_t)32 * 2048 * 64 * 2;
constexpr size_t B_S    = (size_t)32 * 2048 * 2048 * 2;
constexpr size_t B_COL  = (size_t)32 * 2048 * 4;
constexpr size_t O_H    = 0;
constexpr size_t O_H2   = O_H   + B_ROWC;
constexpr size_t O_AO   = O_H2  + B_ROWC;
constexpr size_t O_FF   = O_AO  + B_ROWC;
constexpr size_t O_Q    = O_FF  + B_FF;
constexpr size_t O_K    = O_Q   + B_QKV;
constexpr size_t O_VT   = O_K   + B_QKV;
constexpr size_t O_WQKV = O_VT  + B_QKV;
constexpr size_t O_WOT  = O_WQKV + (size_t)1536*512*2;
constexpr size_t O_W1T  = O_WOT  + (size_t)512*512*2;
constexpr size_t O_W2T  = O_W1T  + (size_t)2048*512*2;
constexpr size_t O_S    = O_W2T  + (size_t)512*2048*2;
constexpr size_t O_M    = O_S   + B_S;
constexpr size_t O_L    = O_M   + B_COL;
constexpr size_t O_X2   = O_L   + B_COL;
constexpr size_t O_PM   = O_X2  + (size_t)8192*512*4;          // pmax [32][32][2048] f32
constexpr size_t O_PS   = O_PM  + (size_t)32*32*2048*4;        // psum [16][32][2048] f32
constexpr size_t SZ_ALL = O_PS  + (size_t)16*32*2048*4;

__device__ __align__(128) unsigned char g_s[SZ_ALL];

// ---------------- helpers ----------------
DINL uint32_t smem_u32(const void* p) {
    uint32_t a;
    asm("{ .reg .u64 t; cvta.to.shared.u64 t, %1; cvt.u32.u64 %0, t; }" : "=r"(a) : "l"(p));
    return a;
}
DINL uint32_t sw128(uint32_t off) { return off ^ ((off >> 3) & 0x70); }

DINL void ldsm4(uint32_t* r, uint32_t a) {
    asm volatile("ldmatrix.sync.aligned.m8n8.x4.shared.b16 {%0,%1,%2,%3}, [%4];"
        : "=r"(r[0]), "=r"(r[1]), "=r"(r[2]), "=r"(r[3]) : "r"(a));
}
DINL void mma16816(float* d, const uint32_t* a, const uint32_t* b) {
    asm volatile("mma.sync.aligned.m16n8k16.row.col.f32.f16.f16.f32 "
        "{%0,%1,%2,%3},{%4,%5,%6,%7},{%8,%9},{%0,%1,%2,%3};"
        : "+f"(d[0]), "+f"(d[1]), "+f"(d[2]), "+f"(d[3])
        : "r"(a[0]), "r"(a[1]), "r"(a[2]), "r"(a[3]), "r"(b[0]), "r"(b[1]));
}
DINL uint32_t pack2(float a, float b) {
    union { __half2 h; uint32_t u; } cv;
    cv.h = __floats2half2_rn(a, b);
    return cv.u;
}
template<int NR>
DINL void ld_tile(const __half* __restrict__ g, int ldh, char* __restrict__ smp, int tid) {
    #pragma unroll
    for (int p = 0; p < NR / 32; p++) {
        int u = tid + (p << 8), r = u >> 3, cc = u & 7;
        *reinterpret_cast<uint4*>(smp + sw128((uint32_t)(r << 7) + (cc << 4))) =
            *reinterpret_cast<const uint4*>(g + (size_t)r * ldh + (cc << 3));
    }
}
template<int NR>
DINL void ldg_tile(const __half* __restrict__ g, int ldh, uint4* v, int tid) {
    #pragma unroll
    for (int p = 0; p < NR / 32; p++) {
        int u = tid + (p << 8), r = u >> 3, cc = u & 7;
        v[p] = *reinterpret_cast<const uint4*>(g + (size_t)r * ldh + (cc << 3));
    }
}
template<int NR>
DINL void sts_tile(char* __restrict__ smp, const uint4* v, int tid) {
    #pragma unroll
    for (int p = 0; p < NR / 32; p++) {
        int u = tid + (p << 8), r = u >> 3, cc = u & 7;
        *reinterpret_cast<uint4*>(smp + sw128((uint32_t)(r << 7) + (cc << 4))) = v[p];
    }
}
DINL void ldA(uint32_t buf, int lane, int m0, int ks, uint32_t a[4][4]) {
    int row = m0 + (lane & 15);
    uint32_t koff = (uint32_t)(ks << 5) + ((lane & 16) ? 16u : 0u);
    #pragma unroll
    for (int mt = 0; mt < 4; mt++)
        ldsm4(a[mt], buf + sw128((uint32_t)((row + mt * 16) << 7) + koff));
}
DINL void ldB16(uint32_t buf, int lane, int n0, int ks, uint32_t b[4]) {
    int row = n0 + (lane & 7) + ((lane & 16) >> 1);
    uint32_t koff = (uint32_t)(ks << 5) + ((lane & 8) << 1);
    ldsm4(b, buf + sw128((uint32_t)(row << 7) + koff));
}
DINL void mma_chunk(uint32_t abuf, uint32_t bbuf, int lane, int wm, int wn, float acc[4][4][4]) {
    #pragma unroll
    for (int ks = 0; ks < 4; ks++) {
        uint32_t a[4][4], b[2][4];
        ldA(abuf, lane, wm * 64, ks, a);
        ldB16(bbuf, lane, wn * 32, ks, b[0]);
        ldB16(bbuf, lane, wn * 32 + 16, ks, b[1]);
        #pragma unroll
        for (int mt = 0; mt < 4; mt++)
            #pragma unroll
            for (int nt = 0; nt < 4; nt++)
                mma16816(acc[mt][nt], a[mt], &b[nt >> 1][(nt & 1) * 2]);
    }
}

// ---------------- LayerNorm fp32 -> fp16 ----------------
__global__ __launch_bounds__(256) void ln_h(
    const float* __restrict__ x, const float* __restrict__ g,
    const float* __restrict__ be, __half* __restrict__ o)
{
    const int row = blockIdx.x, t = threadIdx.x;
    const float* xr = x + (size_t)row * CE;
    float2 ab = *reinterpret_cast<const float2*>(xr + 2 * t);
    float s = ab.x + ab.y, sq = ab.x * ab.x + ab.y * ab.y;
    #pragma unroll
    for (int off = 16; off; off >>= 1) {
        s  += __shfl_xor_sync(~0u, s, off);
        sq += __shfl_xor_sync(~0u, sq, off);
    }
    __shared__ float sh[16];
    if ((t & 31) == 0) { sh[t >> 5] = s; sh[8 + (t >> 5)] = sq; }
    __syncthreads();
    if (t == 0) {
        float S = 0, Q = 0;
        #pragma unroll
        for (int i = 0; i < 8; i++) { S += sh[i]; Q += sh[8 + i]; }
        sh[0] = S; sh[8] = Q;
    }
    __syncthreads();
    float mu = sh[0] * (1.f / 512), var = sh[8] * (1.f / 512) - mu * mu;
    float inv = rsqrtf(var + 1e-5f);
    float o0 = (ab.x - mu) * inv * g[2 * t] + be[2 * t];
    float o1 = (ab.y - mu) * inv * g[2 * t + 1] + be[2 * t + 1];
    *reinterpret_cast<__half2*>(o + (size_t)row * CE + 2 * t) = __floats2half2_rn(o0, o1);
}

// ---------------- weight prep ----------------
__global__ void packqkv(const float* __restrict__ Wq, const float* __restrict__ Wk,
                        const float* __restrict__ Wv, __half* __restrict__ wt)
{
    __shared__ float tl[32][33];
    int c0 = blockIdx.x << 5, d0 = blockIdx.y << 5, z = blockIdx.z;
    int which = z >> 3, h = z & 7;
    const float* W = which == 0 ? Wq : (which == 1 ? Wk : Wv);
    float sc = which == 0 ? 0.04419417382415922f : 1.f;
    tl[threadIdx.y][threadIdx.x] =
        W[((size_t)h * 512 + c0 + threadIdx.y) * 64 + d0 + threadIdx.x] * sc;
    __syncthreads();
    wt[((size_t)(which * 512 + h * 64 + d0 + threadIdx.y)) * 512 + c0 + threadIdx.x] =
        __float2half(tl[threadIdx.x][threadIdx.y]);
}
__global__ void tr_kernel(const float* __restrict__ in, __half* __restrict__ out, int K, int N)
{
    __shared__ float tl[32][33];
    int n0 = blockIdx.x << 5, k0 = blockIdx.y << 5;
    tl[threadIdx.y][threadIdx.x] = in[(size_t)(k0 + threadIdx.y) * N + n0 + threadIdx.x];
    __syncthreads();
    out[(size_t)(n0 + threadIdx.y) * K + k0 + threadIdx.x] = __float2half(tl[threadIdx.x][threadIdx.y]);
}

// ---------------- GEMM ----------------
template<int MODE>
__global__ __launch_bounds__(256) void gemm_mma(
    const __half* __restrict__ A, const __half* __restrict__ B, int K,
    const float* __restrict__ bias, const float* __restrict__ res,
    float* __restrict__ outf, __half* __restrict__ outh,
    __half* __restrict__ oq, __half* __restrict__ ok2, __half* __restrict__ ov)
{
    extern __shared__ __align__(1024) char sm[];
    const uint32_t sb = smem_u32(sm);
    const int tid = threadIdx.x, lane = tid & 31, w = tid >> 5;
    const int wm = w & 1, wn = w >> 1;
    const int m0 = blockIdx.y << 7, n0 = blockIdx.x << 7;
    const __half* Ab = A + (size_t)m0 * K;
    const __half* Bb = B + (size_t)n0 * K;
    float acc[4][4][4];
    #pragma unroll
    for (int i = 0; i < 4; i++)
        #pragma unroll
        for (int j = 0; j < 4; j++)
            #pragma unroll
            for (int e = 0; e < 4; e++) acc[i][j][e] = 0.f;

    ld_tile<128>(Ab, K, sm, tid);
    ld_tile<128>(Bb, K, sm + 32768, tid);
    __syncthreads();
    const int nc = K >> 6;
    for (int c = 0; c < nc; c++) {
        uint4 va[4], vb[4];
        if (c + 1 < nc) {
            ldg_tile<128>(Ab + ((c + 1) << 6), K, va, tid);
            ldg_tile<128>(Bb + ((c + 1) << 6), K, vb, tid);
        }
        mma_chunk(sb + ((uint32_t)(c & 1) << 14), sb + 32768 + ((uint32_t)(c & 1) << 14),
                  lane, wm, wn, acc);
        __syncthreads();
        if (c + 1 < nc) {
            sts_tile<128>(sm + (((c + 1) & 1) << 14), va, tid);
            sts_tile<128>(sm + 32768 + (((c + 1) & 1) << 14), vb, tid);
        }
        __syncthreads();
    }
    const int gm = lane >> 2, gn2 = (lane & 3) << 1;
    #pragma unroll
    for (int mt = 0; mt < 4; mt++) {
        #pragma unroll
        for (int nt = 0; nt < 4; nt++) {
            #pragma unroll
            for (int hf = 0; hf < 2; hf++) {
                const int m = m0 + wm * 64 + mt * 16 + gm + hf * 8;
                const int n = n0 + wn * 32 + nt * 8 + gn2;
                float v0 = acc[mt][nt][hf * 2 + 0], v1 = acc[mt][nt][hf * 2 + 1];
                if (MODE == 1) {
                    size_t ri = (size_t)m * 512 + n;
                    float2 o = { v0 + bias[n] + res[ri], v1 + bias[n + 1] + res[ri + 1] };
                    *reinterpret_cast<float2*>(outf + ri) = o;
                } else if (MODE == 2) {
                    *reinterpret_cast<uint32_t*>(outh + (size_t)m * 2048 + n) =
                        pack2(fmaxf(v0 + bias[n], 0.f), fmaxf(v1 + bias[n + 1], 0.f));
                } else {
                    int which = n0 >> 9;
                    int hh = (n & 511) >> 6, d = n & 63;
                    int b = m >> 11, t2 = m & 2047;
                    int bh = (b << 3) + hh;
                    if (which < 2) {
                        __half* dst = which == 0 ? oq : ok2;
                        *reinterpret_cast<uint32_t*>(dst + ((size_t)bh * 2048 + t2) * 64 + d) =
                            pack2(v0, v1);
                    } else {
                        ov[((size_t)bh * 64 + d) * 2048 + t2]     = __float2half(v0);
                        ov[((size_t)bh * 64 + d + 1) * 2048 + t2] = __float2half(v1);
                    }
                }
            }
        }
    }
}

// ---------------- scores + per-64row column-max partials ----------------
__global__ __launch_bounds__(256) void score_mma(
    const __half* __restrict__ q, const __half* __restrict__ k,
    __half* __restrict__ S, float* __restrict__ pmax)
{
    extern __shared__ __align__(1024) char sm[];
    const uint32_t sb = smem_u32(sm);
    const int tid = threadIdx.x, lane = tid & 31, w = tid >> 5;
    const int wm = w & 1, wn = w >> 1;
    const int tt = (int)gridDim.x - 1 - (int)blockIdx.x, bh = blockIdx.y;
    const __half* qb = q + ((size_t)bh * TS + (size_t)tt * 128) * 64;
    const __half* kb = k + (size_t)bh * TS * 64;
    __half* Sb = S + (size_t)bh * TS * TS;

    ld_tile<128>(qb, 64, sm, tid);
    ld_tile<128>(kb, 64, sm + 16384, tid);
    __syncthreads();
    const int gm = lane >> 2, gn2 = (lane & 3) << 1;
    for (int st = 0; st <= tt; st++) {
        uint4 vk[4];
        if (st < tt) ldg_tile<128>(kb + (size_t)(st + 1) * 128 * 64, 64, vk, tid);
        float acc[4][4][4];
        #pragma unroll
        for (int i = 0; i < 4; i++)
            #pragma unroll
            for (int j = 0; j < 4; j++)
                #pragma unroll
                for (int e = 0; e < 4; e++) acc[i][j][e] = 0.f;
        mma_chunk(sb, sb + 16384 + ((uint32_t)(st & 1) << 14), lane, wm, wn, acc);
        if (st == tt) {  // apply causal mask into acc
            #pragma unroll
            for (int mt = 0; mt < 4; mt++)
                #pragma unroll
                for (int nt = 0; nt < 4; nt++)
                    #pragma unroll
                    for (int hf = 0; hf < 2; hf++) {
                        const int t2 = tt * 128 + wm * 64 + mt * 16 + gm + hf * 8;
                        const int s  = st * 128 + wn * 32 + nt * 8 + gn2;
                        if (s > t2)     acc[mt][nt][hf * 2 + 0] = -30000.f;
                        if (s + 1 > t2) acc[mt][nt][hf * 2 + 1] = -30000.f;
                    }
        }
        #pragma unroll
        for (int mt = 0; mt < 4; mt++)
            #pragma unroll
            for (int nt = 0; nt < 4; nt++)
                #pragma unroll
                for (int hf = 0; hf < 2; hf++) {
                    const int t2 = tt * 128 + wm * 64 + mt * 16 + gm + hf * 8;
                    const int s  = st * 128 + wn * 32 + nt * 8 + gn2;
                    *reinterpret_cast<uint32_t*>(Sb + (size_t)t2 * TS + s) =
                        pack2(acc[mt][nt][hf * 2 + 0], acc[mt][nt][hf * 2 + 1]);
                }
        // per-warp (64-row) column max -> pmax[tt*2+wm][bh][s]
        #pragma unroll
        for (int nt = 0; nt < 4; nt++) {
            float m0 = -3.4e38f, m1 = -3.4e38f;
            #pragma unroll
            for (int mt = 0; mt < 4; mt++) {
                m0 = fmaxf(m0, fmaxf(acc[mt][nt][0], acc[mt][nt][2]));
                m1 = fmaxf(m1, fmaxf(acc[mt][nt][1], acc[mt][nt][3]));
            }
            #pragma unroll
            for (int o = 4; o < 32; o <<= 1) {
                m0 = fmaxf(m0, __shfl_xor_sync(~0u, m0, o));
                m1 = fmaxf(m1, __shfl_xor_sync(~0u, m1, o));
            }
            if (lane < 4) {
                const int s = st * 128 + wn * 32 + nt * 8 + gn2;
                float* pm = pmax + ((size_t)(tt * 2 + wm) * 32 + bh) * TS + s;
                pm[0] = m0; pm[1] = m1;
            }
        }
        __syncthreads();
        if (st < tt) sts_tile<128>(sm + 16384 + (((st + 1) & 1) << 14), vk, tid);
        __syncthreads();
    }
}

// ---------------- combine column max ----------------
__global__ __launch_bounds__(256) void combine_max(
    const float* __restrict__ pmax, float* __restrict__ mc)
{
    const int bh = blockIdx.y, s = blockIdx.x * 256 + threadIdx.x;
    const int p0 = (s >> 7) << 1;
    float m = -3.4e38f;
    for (int p = p0; p < 32; p++)
        m = fmaxf(m, pmax[((size_t)p * 32 + bh) * TS + s]);
    mc[(size_t)bh * TS + s] = m;
}

// ---------------- E = exp(S - m), in place; per-128row-tile column sums ----
__global__ __launch_bounds__(256) void expsum_k(
    __half* __restrict__ S, const float* __restrict__ mc, float* __restrict__ psum)
{
    const int st = blockIdx.x, tt = blockIdx.y, bh = blockIdx.z;
    if (st > tt) return;
    const int tid = threadIdx.x;
    __half* Sb = S + ((size_t)bh * TS + (size_t)tt * 128) * TS + (size_t)st * 128;
    const int c  = (tid & 63) << 1;
    const int r0 = (tid >> 6) << 5;
    const float m0 = mc[(size_t)bh * TS + st * 128 + c];
    const float m1 = mc[(size_t)bh * TS + st * 128 + c + 1];
    float s0 = 0.f, s1 = 0.f;
    for (int r = r0; r < r0 + 32; r++) {
        uint32_t* p = reinterpret_cast<uint32_t*>(Sb + (size_t)r * TS + c);
        union { uint32_t u; __half2 h; } cv; cv.u = *p;
        float2 f = __half22float2(cv.h);
        float e0 = __expf(f.x - m0), e1 = __expf(f.y - m1);
        s0 += e0; s1 += e1;
        *p = pack2(e0, e1);
    }
    __shared__ float red[4][128];
    red[tid >> 6][((tid & 63) << 1)]     = s0;
    red[tid >> 6][((tid & 63) << 1) + 1] = s1;
    __syncthreads();
    if (tid < 128) {
        float t = red[0][tid] + red[1][tid] + red[2][tid] + red[3][tid];
        psum[((size_t)tt * 32 + bh) * TS + st * 128 + tid] = t;
    }
}

// ---------------- combine column sums -> 1/l ----------------
__global__ __launch_bounds__(256) void combine_sum(
    const float* __restrict__ psum, float* __restrict__ lc)
{
    const int bh = blockIdx.y, s = blockIdx.x * 256 + threadIdx.x;
    float l = 0.f;
    for (int t = s >> 7; t < 16; t++)
        l += psum[((size_t)t * 32 + bh) * TS + s];
    lc[(size_t)bh * TS + s] = 1.f / l;
}

// ---------------- PV: P = E * linv, out = P @ Vt^T ----------------
__global__ __launch_bounds__(256) void pv_mma(
    const __half* __restrict__ S, const __half* __restrict__ Vt,
    const float* __restrict__ lc, __half* __restrict__ ao)
{
    extern __shared__ __align__(1024) char sm[];
    float* smL = reinterpret_cast<float*>(sm);
    char* Pt = sm + 1024;
    char* Vtile = sm + 1024 + 16384;
    const uint32_t ptb = smem_u32(Pt), vtb = smem_u32(Vtile);
    const int tid = threadIdx.x, lane = tid & 31, w = tid >> 5;
    const int wm = w & 1, wn = w >> 1;
    const int tt = (int)gridDim.x - 1 - (int)blockIdx.x, bh = blockIdx.y;
    const __half* Sb = S + ((size_t)bh * TS + (size_t)tt * 128) * TS;
    const __half* Vb = Vt + (size_t)bh * 64 * TS;
    const float* lb = lc + (size_t)bh * TS;

    float acc[4][2][4];
    #pragma unroll
    for (int i = 0; i < 4; i++)
        #pragma unroll
        for (int j = 0; j < 2; j++)
            #pragma unroll
            for (int e = 0; e < 4; e++) acc[i][j][e] = 0.f;

    const int nch = 2 * (tt + 1);
    for (int c = 0; c < nch; c++) {
        __syncthreads();
        if (tid < 64) smL[tid] = lb[c * 64 + tid];
        ld_tile<64>(Vb + c * 64, TS, Vtile, tid);
        __syncthreads();
        #pragma unroll
        for (int p = 0; p < 4; p++) {
            int u = tid + (p << 8), r = u >> 3, cc = u & 7;
            uint4 sv = *reinterpret_cast<const uint4*>(Sb + (size_t)r * TS + c * 64 + (cc << 3));
            const __half2* hp = reinterpret_cast<const __half2*>(&sv);
            uint32_t pk[4];
            #pragma unroll
            for (int j = 0; j < 4; j++) {
                float2 f = __half22float2(hp[j]);
                int s0 = (cc << 3) + 2 * j;
                pk[j] = pack2(f.x * smL[s0], f.y * smL[s0 + 1]);
            }
            *reinterpret_cast<uint4*>(Pt + sw128((uint32_t)(r << 7) + (cc << 4))) =
                make_uint4(pk[0], pk[1], pk[2], pk[3]);
        }
        __syncthreads();
        #pragma unroll
        for (int ks = 0; ks < 4; ks++) {
            uint32_t a[4][4], b[4];
            ldA(ptb, lane, wm * 64, ks, a);
            ldB16(vtb, lane, wn * 16, ks, b);
            #pragma unroll
            for (int mt = 0; mt < 4; mt++) {
                mma16816(acc[mt][0], a[mt], &b[0]);
                mma16816(acc[mt][1], a[mt], &b[2]);
            }
        }
    }
    const int gm = lane >> 2, gn2 = (lane & 3) << 1;
    #pragma unroll
    for (int mt = 0; mt < 4; mt++) {
        #pragma unroll
        for (int nt = 0; nt < 2; nt++) {
            #pragma unroll
            for (int hf = 0; hf < 2; hf++) {
                const int t2 = tt * 128 + wm * 64 + mt * 16 + gm + hf * 8;
                const int n = wn * 16 + nt * 8 + gn2;
                *reinterpret_cast<uint32_t*>(
                    ao + ((size_t)(bh >> 3) * TS + t2) * 512 + (bh & 7) * 64 + n) =
                    pack2(acc[mt][nt][hf * 2 + 0], acc[mt][nt][hf * 2 + 1]);
            }
        }
    }
}

// ---------------- launcher ----------------
extern "C" void kernel_launch(void* const* d_in, const int* in_sizes, int n_in,
                              void* d_out, int out_size)
{
    const float* x  = (const float*)d_in[0];
    const float* Wq = (const float*)d_in[1];
    const float* Wk = (const float*)d_in[2];
    const float* Wv = (const float*)d_in[3];
    const float* Wo = (const float*)d_in[4];
    const float* bo = (const float*)d_in[5];
    const float* W1 = (const float*)d_in[6];
    const float* b1 = (const float*)d_in[7];
    const float* W2 = (const float*)d_in[8];
    const float* b2 = (const float*)d_in[9];
    const float* g1 = (const float*)d_in[10];
    const float* be1= (const float*)d_in[11];
    const float* g2 = (const float*)d_in[12];
    const float* be2= (const float*)d_in[13];
    float* out = (float*)d_out;

    void* sp = nullptr;
    cudaGetSymbolAddress(&sp, g_s);
    unsigned char* b = (unsigned char*)sp;
    __half* p_h   = (__half*)(b + O_H);
    __half* p_h2  = (__half*)(b + O_H2);
    __half* p_ao  = (__half*)(b + O_AO);
    __half* p_ff  = (__half*)(b + O_FF);
    __half* p_q   = (__half*)(b + O_Q);
    __half* p_k   = (__half*)(b + O_K);
    __half* p_vt  = (__half*)(b + O_VT);
    __half* p_wqkv= (__half*)(b + O_WQKV);
    __half* p_wot = (__half*)(b + O_WOT);
    __half* p_w1t = (__half*)(b + O_W1T);
    __half* p_w2t = (__half*)(b + O_W2T);
    __half* p_S   = (__half*)(b + O_S);
    float*  p_m   = (float*)(b + O_M);
    float*  p_l   = (float*)(b + O_L);
    float*  p_x2  = (float*)(b + O_X2);
    float*  p_pm  = (float*)(b + O_PM);
    float*  p_ps  = (float*)(b + O_PS);

    cudaFuncSetAttribute(gemm_mma<0>, cudaFuncAttributeMaxDynamicSharedMemorySize, 65536);
    cudaFuncSetAttribute(gemm_mma<1>, cudaFuncAttributeMaxDynamicSharedMemorySize, 65536);
    cudaFuncSetAttribute(gemm_mma<2>, cudaFuncAttributeMaxDynamicSharedMemorySize, 65536);
    cudaFuncSetAttribute(score_mma,   cudaFuncAttributeMaxDynamicSharedMemorySize, 49152);
    cudaFuncSetAttribute(pv_mma,      cudaFuncAttributeMaxDynamicSharedMemorySize, 25600);

    dim3 b32(32, 32);
    ln_h<<<8192, 256>>>(x, g1, be1, p_h);
    packqkv<<<dim3(16, 2, 24), b32>>>(Wq, Wk, Wv, p_wqkv);
    tr_kernel<<<dim3(16, 16), b32>>>(Wo, p_wot, 512, 512);
    tr_kernel<<<dim3(64, 16), b32>>>(W1, p_w1t, 512, 2048);
    tr_kernel<<<dim3(16, 64), b32>>>(W2, p_w2t, 2048, 512);
    gemm_mma<0><<<dim3(12, 64), 256, 65536>>>(p_h, p_wqkv, 512, nullptr, nullptr,
                                              nullptr, nullptr, p_q, p_k, p_vt);
    score_mma<<<dim3(16, 32), 256, 49152>>>(p_q, p_k, p_S, p_pm);
    combine_max<<<dim3(8, 32), 256>>>(p_pm, p_m);
    expsum_k<<<dim3(16, 16, 32), 256>>>(p_S, p_m, p_ps);
    combine_sum<<<dim3(8, 32), 256>>>(p_ps, p_l);
    pv_mma<<<dim3(16, 32), 256, 25600>>>(p_S, p_vt, p_l, p_ao);
    gemm_mma<1><<<dim3(4, 64), 256, 65536>>>(p_ao, p_wot, 512, bo, x,
                                             p_x2, nullptr, nullptr, nullptr, nullptr);
    ln_h<<<8192, 256>>>(p_x2, g2, be2, p_h2);
    gemm_mma<2><<<dim3(16, 64), 256, 65536>>>(p_h2, p_w1t, 512, b1, nullptr,
                                              nullptr, p_ff, nullptr, nullptr, nullptr);
    gemm_mma<1><<<dim3(4, 64), 256, 65536>>>(p_ff, p_w2t, 2048, b2, p_x2,
                                             out, nullptr, nullptr, nullptr, nullptr);
}

// round 6
// speedup vs baseline: 5.1021x; 1.1740x over previous
#include <cuda_runtime.h>
#include <cuda_fp16.h>
#include <cstdint>
#include <cstddef>

#define TS 2048
#define CE 512
#define DINL __device__ __forceinline__

// ---------------- scratch (bytes) ----------------
constexpr size_t B_ROWC = (size_t)8192 * 512 * 2;
constexpr size_t B_FF   = (size_t)8192 * 2048 * 2;
constexpr size_t B_QKV  = (size_t)32 * 2048 * 64 * 2;
constexpr size_t B_S    = (size_t)32 * 2048 * 2048 * 2;
constexpr size_t B_COL  = (size_t)32 * 2048 * 4;
constexpr size_t O_H    = 0;
constexpr size_t O_H2   = O_H   + B_ROWC;
constexpr size_t O_AO   = O_H2  + B_ROWC;
constexpr size_t O_FF   = O_AO  + B_ROWC;
constexpr size_t O_Q    = O_FF  + B_FF;
constexpr size_t O_K    = O_Q   + B_QKV;
constexpr size_t O_VT   = O_K   + B_QKV;
constexpr size_t O_WQKV = O_VT  + B_QKV;
constexpr size_t O_WOT  = O_WQKV + (size_t)1536*512*2;
constexpr size_t O_W1T  = O_WOT  + (size_t)512*512*2;
constexpr size_t O_W2T  = O_W1T  + (size_t)2048*512*2;
constexpr size_t O_S    = O_W2T  + (size_t)512*2048*2;
constexpr size_t O_L    = O_S   + B_S;
constexpr size_t O_X2   = O_L   + B_COL;
constexpr size_t O_PS   = O_X2  + (size_t)8192*512*4;          // psum [32][32][2048] f32
constexpr size_t SZ_ALL = O_PS  + (size_t)32*32*2048*4;

__device__ __align__(128) unsigned char g_s[SZ_ALL];

// ---------------- helpers ----------------
DINL uint32_t smem_u32(const void* p) {
    uint32_t a;
    asm("{ .reg .u64 t; cvta.to.shared.u64 t, %1; cvt.u32.u64 %0, t; }" : "=r"(a) : "l"(p));
    return a;
}
DINL uint32_t sw128(uint32_t off) { return off ^ ((off >> 3) & 0x70); }

DINL void ldsm4(uint32_t* r, uint32_t a) {
    asm volatile("ldmatrix.sync.aligned.m8n8.x4.shared.b16 {%0,%1,%2,%3}, [%4];"
        : "=r"(r[0]), "=r"(r[1]), "=r"(r[2]), "=r"(r[3]) : "r"(a));
}
DINL void mma16816(float* d, const uint32_t* a, const uint32_t* b) {
    asm volatile("mma.sync.aligned.m16n8k16.row.col.f32.f16.f16.f32 "
        "{%0,%1,%2,%3},{%4,%5,%6,%7},{%8,%9},{%0,%1,%2,%3};"
        : "+f"(d[0]), "+f"(d[1]), "+f"(d[2]), "+f"(d[3])
        : "r"(a[0]), "r"(a[1]), "r"(a[2]), "r"(a[3]), "r"(b[0]), "r"(b[1]));
}
DINL uint32_t pack2(float a, float b) {
    union { __half2 h; uint32_t u; } cv;
    cv.h = __floats2half2_rn(a, b);
    return cv.u;
}
template<int NR>
DINL void ld_tile(const __half* __restrict__ g, int ldh, char* __restrict__ smp, int tid) {
    #pragma unroll
    for (int p = 0; p < NR / 32; p++) {
        int u = tid + (p << 8), r = u >> 3, cc = u & 7;
        *reinterpret_cast<uint4*>(smp + sw128((uint32_t)(r << 7) + (cc << 4))) =
            *reinterpret_cast<const uint4*>(g + (size_t)r * ldh + (cc << 3));
    }
}
template<int NR>
DINL void ldg_tile(const __half* __restrict__ g, int ldh, uint4* v, int tid) {
    #pragma unroll
    for (int p = 0; p < NR / 32; p++) {
        int u = tid + (p << 8), r = u >> 3, cc = u & 7;
        v[p] = *reinterpret_cast<const uint4*>(g + (size_t)r * ldh + (cc << 3));
    }
}
template<int NR>
DINL void sts_tile(char* __restrict__ smp, const uint4* v, int tid) {
    #pragma unroll
    for (int p = 0; p < NR / 32; p++) {
        int u = tid + (p << 8), r = u >> 3, cc = u & 7;
        *reinterpret_cast<uint4*>(smp + sw128((uint32_t)(r << 7) + (cc << 4))) = v[p];
    }
}
DINL void ldA(uint32_t buf, int lane, int m0, int ks, uint32_t a[4][4]) {
    int row = m0 + (lane & 15);
    uint32_t koff = (uint32_t)(ks << 5) + ((lane & 16) ? 16u : 0u);
    #pragma unroll
    for (int mt = 0; mt < 4; mt++)
        ldsm4(a[mt], buf + sw128((uint32_t)((row + mt * 16) << 7) + koff));
}
DINL void ldB16(uint32_t buf, int lane, int n0, int ks, uint32_t b[4]) {
    int row = n0 + (lane & 7) + ((lane & 16) >> 1);
    uint32_t koff = (uint32_t)(ks << 5) + ((lane & 8) << 1);
    ldsm4(b, buf + sw128((uint32_t)(row << 7) + koff));
}
DINL void mma_chunk(uint32_t abuf, uint32_t bbuf, int lane, int wm, int wn, float acc[4][4][4]) {
    #pragma unroll
    for (int ks = 0; ks < 4; ks++) {
        uint32_t a[4][4], b[2][4];
        ldA(abuf, lane, wm * 64, ks, a);
        ldB16(bbuf, lane, wn * 32, ks, b[0]);
        ldB16(bbuf, lane, wn * 32 + 16, ks, b[1]);
        #pragma unroll
        for (int mt = 0; mt < 4; mt++)
            #pragma unroll
            for (int nt = 0; nt < 4; nt++)
                mma16816(acc[mt][nt], a[mt], &b[nt >> 1][(nt & 1) * 2]);
    }
}

// ---------------- LayerNorm fp32 -> fp16 ----------------
__global__ __launch_bounds__(256) void ln_h(
    const float* __restrict__ x, const float* __restrict__ g,
    const float* __restrict__ be, __half* __restrict__ o)
{
    const int row = blockIdx.x, t = threadIdx.x;
    const float* xr = x + (size_t)row * CE;
    float2 ab = *reinterpret_cast<const float2*>(xr + 2 * t);
    float s = ab.x + ab.y, sq = ab.x * ab.x + ab.y * ab.y;
    #pragma unroll
    for (int off = 16; off; off >>= 1) {
        s  += __shfl_xor_sync(~0u, s, off);
        sq += __shfl_xor_sync(~0u, sq, off);
    }
    __shared__ float sh[16];
    if ((t & 31) == 0) { sh[t >> 5] = s; sh[8 + (t >> 5)] = sq; }
    __syncthreads();
    if (t == 0) {
        float S = 0, Q = 0;
        #pragma unroll
        for (int i = 0; i < 8; i++) { S += sh[i]; Q += sh[8 + i]; }
        sh[0] = S; sh[8] = Q;
    }
    __syncthreads();
    float mu = sh[0] * (1.f / 512), var = sh[8] * (1.f / 512) - mu * mu;
    float inv = rsqrtf(var + 1e-5f);
    float o0 = (ab.x - mu) * inv * g[2 * t] + be[2 * t];
    float o1 = (ab.y - mu) * inv * g[2 * t + 1] + be[2 * t + 1];
    *reinterpret_cast<__half2*>(o + (size_t)row * CE + 2 * t) = __floats2half2_rn(o0, o1);
}

// ---------------- weight prep ----------------
__global__ void packqkv(const float* __restrict__ Wq, const float* __restrict__ Wk,
                        const float* __restrict__ Wv, __half* __restrict__ wt)
{
    __shared__ float tl[32][33];
    int c0 = blockIdx.x << 5, d0 = blockIdx.y << 5, z = blockIdx.z;
    int which = z >> 3, h = z & 7;
    const float* W = which == 0 ? Wq : (which == 1 ? Wk : Wv);
    float sc = which == 0 ? 0.04419417382415922f : 1.f;
    tl[threadIdx.y][threadIdx.x] =
        W[((size_t)h * 512 + c0 + threadIdx.y) * 64 + d0 + threadIdx.x] * sc;
    __syncthreads();
    wt[((size_t)(which * 512 + h * 64 + d0 + threadIdx.y)) * 512 + c0 + threadIdx.x] =
        __float2half(tl[threadIdx.x][threadIdx.y]);
}
__global__ void tr_kernel(const float* __restrict__ in, __half* __restrict__ out, int K, int N)
{
    __shared__ float tl[32][33];
    int n0 = blockIdx.x << 5, k0 = blockIdx.y << 5;
    tl[threadIdx.y][threadIdx.x] = in[(size_t)(k0 + threadIdx.y) * N + n0 + threadIdx.x];
    __syncthreads();
    out[(size_t)(n0 + threadIdx.y) * K + k0 + threadIdx.x] = __float2half(tl[threadIdx.x][threadIdx.y]);
}

// ---------------- GEMM ----------------
template<int MODE>
__global__ __launch_bounds__(256) void gemm_mma(
    const __half* __restrict__ A, const __half* __restrict__ B, int K,
    const float* __restrict__ bias, const float* __restrict__ res,
    float* __restrict__ outf, __half* __restrict__ outh,
    __half* __restrict__ oq, __half* __restrict__ ok2, __half* __restrict__ ov)
{
    extern __shared__ __align__(1024) char sm[];
    const uint32_t sb = smem_u32(sm);
    const int tid = threadIdx.x, lane = tid & 31, w = tid >> 5;
    const int wm = w & 1, wn = w >> 1;
    const int m0 = blockIdx.y << 7, n0 = blockIdx.x << 7;
    const __half* Ab = A + (size_t)m0 * K;
    const __half* Bb = B + (size_t)n0 * K;
    float acc[4][4][4];
    #pragma unroll
    for (int i = 0; i < 4; i++)
        #pragma unroll
        for (int j = 0; j < 4; j++)
            #pragma unroll
            for (int e = 0; e < 4; e++) acc[i][j][e] = 0.f;

    ld_tile<128>(Ab, K, sm, tid);
    ld_tile<128>(Bb, K, sm + 32768, tid);
    __syncthreads();
    const int nc = K >> 6;
    for (int c = 0; c < nc; c++) {
        uint4 va[4], vb[4];
        if (c + 1 < nc) {
            ldg_tile<128>(Ab + ((c + 1) << 6), K, va, tid);
            ldg_tile<128>(Bb + ((c + 1) << 6), K, vb, tid);
        }
        mma_chunk(sb + ((uint32_t)(c & 1) << 14), sb + 32768 + ((uint32_t)(c & 1) << 14),
                  lane, wm, wn, acc);
        __syncthreads();
        if (c + 1 < nc) {
            sts_tile<128>(sm + (((c + 1) & 1) << 14), va, tid);
            sts_tile<128>(sm + 32768 + (((c + 1) & 1) << 14), vb, tid);
        }
        __syncthreads();
    }
    const int gm = lane >> 2, gn2 = (lane & 3) << 1;
    #pragma unroll
    for (int mt = 0; mt < 4; mt++) {
        #pragma unroll
        for (int nt = 0; nt < 4; nt++) {
            #pragma unroll
            for (int hf = 0; hf < 2; hf++) {
                const int m = m0 + wm * 64 + mt * 16 + gm + hf * 8;
                const int n = n0 + wn * 32 + nt * 8 + gn2;
                float v0 = acc[mt][nt][hf * 2 + 0], v1 = acc[mt][nt][hf * 2 + 1];
                if (MODE == 1) {
                    size_t ri = (size_t)m * 512 + n;
                    float2 o = { v0 + bias[n] + res[ri], v1 + bias[n + 1] + res[ri + 1] };
                    *reinterpret_cast<float2*>(outf + ri) = o;
                } else if (MODE == 2) {
                    *reinterpret_cast<uint32_t*>(outh + (size_t)m * 2048 + n) =
                        pack2(fmaxf(v0 + bias[n], 0.f), fmaxf(v1 + bias[n + 1], 0.f));
                } else {
                    int which = n0 >> 9;
                    int hh = (n & 511) >> 6, d = n & 63;
                    int b = m >> 11, t2 = m & 2047;
                    int bh = (b << 3) + hh;
                    if (which < 2) {
                        __half* dst = which == 0 ? oq : ok2;
                        *reinterpret_cast<uint32_t*>(dst + ((size_t)bh * 2048 + t2) * 64 + d) =
                            pack2(v0, v1);
                    } else {
                        ov[((size_t)bh * 64 + d) * 2048 + t2]     = __float2half(v0);
                        ov[((size_t)bh * 64 + d + 1) * 2048 + t2] = __float2half(v1);
                    }
                }
            }
        }
    }
}

// ------- scores: E = exp(q.k) masked, + per-64row column-sum partials -------
__global__ __launch_bounds__(256) void score_mma(
    const __half* __restrict__ q, const __half* __restrict__ k,
    __half* __restrict__ S, float* __restrict__ psum)
{
    extern __shared__ __align__(1024) char sm[];
    const uint32_t sb = smem_u32(sm);
    const int tid = threadIdx.x, lane = tid & 31, w = tid >> 5;
    const int wm = w & 1, wn = w >> 1;
    const int tt = (int)gridDim.x - 1 - (int)blockIdx.x, bh = blockIdx.y;
    const __half* qb = q + ((size_t)bh * TS + (size_t)tt * 128) * 64;
    const __half* kb = k + (size_t)bh * TS * 64;
    __half* Sb = S + (size_t)bh * TS * TS;

    ld_tile<128>(qb, 64, sm, tid);
    ld_tile<128>(kb, 64, sm + 16384, tid);
    __syncthreads();
    const int gm = lane >> 2, gn2 = (lane & 3) << 1;
    for (int st = 0; st <= tt; st++) {
        uint4 vk[4];
        if (st < tt) ldg_tile<128>(kb + (size_t)(st + 1) * 128 * 64, 64, vk, tid);
        float acc[4][4][4];
        #pragma unroll
        for (int i = 0; i < 4; i++)
            #pragma unroll
            for (int j = 0; j < 4; j++)
                #pragma unroll
                for (int e = 0; e < 4; e++) acc[i][j][e] = 0.f;
        mma_chunk(sb, sb + 16384 + ((uint32_t)(st & 1) << 14), lane, wm, wn, acc);
        // exp + mask + store E + per-warp column sums
        #pragma unroll
        for (int nt = 0; nt < 4; nt++) {
            float cs0 = 0.f, cs1 = 0.f;
            const int s = st * 128 + wn * 32 + nt * 8 + gn2;
            #pragma unroll
            for (int mt = 0; mt < 4; mt++) {
                #pragma unroll
                for (int hf = 0; hf < 2; hf++) {
                    const int t2 = tt * 128 + wm * 64 + mt * 16 + gm + hf * 8;
                    float e0 = __expf(acc[mt][nt][hf * 2 + 0]);
                    float e1 = __expf(acc[mt][nt][hf * 2 + 1]);
                    if (st == tt) {
                        if (s > t2)     e0 = 0.f;
                        if (s + 1 > t2) e1 = 0.f;
                    }
                    cs0 += e0; cs1 += e1;
                    *reinterpret_cast<uint32_t*>(Sb + (size_t)t2 * TS + s) = pack2(e0, e1);
                }
            }
            #pragma unroll
            for (int o = 4; o < 32; o <<= 1) {
                cs0 += __shfl_xor_sync(~0u, cs0, o);
                cs1 += __shfl_xor_sync(~0u, cs1, o);
            }
            if (lane < 4) {
                float* pm = psum + ((size_t)(tt * 2 + wm) * 32 + bh) * TS + s;
                pm[0] = cs0; pm[1] = cs1;
            }
        }
        __syncthreads();
        if (st < tt) sts_tile<128>(sm + 16384 + (((st + 1) & 1) << 14), vk, tid);
        __syncthreads();
    }
}

// ---------------- combine column sums -> 1/l ----------------
__global__ __launch_bounds__(256) void combine_sum(
    const float* __restrict__ psum, float* __restrict__ lc)
{
    const int bh = blockIdx.y, s = blockIdx.x * 256 + threadIdx.x;
    const int p0 = (s >> 7) << 1;
    float l = 0.f;
    for (int p = p0; p < 32; p++)
        l += psum[((size_t)p * 32 + bh) * TS + s];
    lc[(size_t)bh * TS + s] = 1.f / l;
}

// ---------------- fold linv into Vt rows (in place) ----------------
__global__ __launch_bounds__(256) void scale_v(
    __half* __restrict__ vt, const float* __restrict__ lc)
{
    const int row = blockIdx.x;           // bh*64 + d
    const int bh = row >> 6;
    __half2* vp = reinterpret_cast<__half2*>(vt + (size_t)row * TS);
    const float2* lp = reinterpret_cast<const float2*>(lc + (size_t)bh * TS);
    #pragma unroll
    for (int i = threadIdx.x; i < 1024; i += 256) {
        float2 l = lp[i];
        float2 v = __half22float2(vp[i]);
        vp[i] = __floats2half2_rn(v.x * l.x, v.y * l.y);
    }
}

// ---------------- PV: plain GEMM out[128,64] = E @ Vs^T ----------------
__global__ __launch_bounds__(256) void pv_mma(
    const __half* __restrict__ S, const __half* __restrict__ Vs,
    __half* __restrict__ ao)
{
    extern __shared__ __align__(1024) char sm[];
    const uint32_t sb = smem_u32(sm);
    const int tid = threadIdx.x, lane = tid & 31, w = tid >> 5;
    const int wm = w & 1, wn = w >> 1;
    const int tt = (int)gridDim.x - 1 - (int)blockIdx.x, bh = blockIdx.y;
    const __half* Ab = S + ((size_t)bh * TS + (size_t)tt * 128) * TS;
    const __half* Bb = Vs + (size_t)bh * 64 * TS;

    float acc[4][2][4];
    #pragma unroll
    for (int i = 0; i < 4; i++)
        #pragma unroll
        for (int j = 0; j < 2; j++)
            #pragma unroll
            for (int e = 0; e < 4; e++) acc[i][j][e] = 0.f;

    ld_tile<128>(Ab, TS, sm, tid);
    ld_tile<64>(Bb, TS, sm + 32768, tid);
    __syncthreads();
    const int nch = 2 * (tt + 1);
    for (int c = 0; c < nch; c++) {
        uint4 va[4], vb[2];
        if (c + 1 < nch) {
            ldg_tile<128>(Ab + (c + 1) * 64, TS, va, tid);
            ldg_tile<64>(Bb + (c + 1) * 64, TS, vb, tid);
        }
        const uint32_t abuf = sb + ((uint32_t)(c & 1) << 14);
        const uint32_t bbuf = sb + 32768 + ((uint32_t)(c & 1) << 13);
        #pragma unroll
        for (int ks = 0; ks < 4; ks++) {
            uint32_t a[4][4], b[4];
            ldA(abuf, lane, wm * 64, ks, a);
            ldB16(bbuf, lane, wn * 16, ks, b);
            #pragma unroll
            for (int mt = 0; mt < 4; mt++) {
                mma16816(acc[mt][0], a[mt], &b[0]);
                mma16816(acc[mt][1], a[mt], &b[2]);
            }
        }
        __syncthreads();
        if (c + 1 < nch) {
            sts_tile<128>(sm + (((c + 1) & 1) << 14), va, tid);
            sts_tile<64>(sm + 32768 + (((c + 1) & 1) << 13), vb, tid);
        }
        __syncthreads();
    }
    const int gm = lane >> 2, gn2 = (lane & 3) << 1;
    #pragma unroll
    for (int mt = 0; mt < 4; mt++) {
        #pragma unroll
        for (int nt = 0; nt < 2; nt++) {
            #pragma unroll
            for (int hf = 0; hf < 2; hf++) {
                const int t2 = tt * 128 + wm * 64 + mt * 16 + gm + hf * 8;
                const int n = wn * 16 + nt * 8 + gn2;
                *reinterpret_cast<uint32_t*>(
                    ao + ((size_t)(bh >> 3) * TS + t2) * 512 + (bh & 7) * 64 + n) =
                    pack2(acc[mt][nt][hf * 2 + 0], acc[mt][nt][hf * 2 + 1]);
            }
        }
    }
}

// ---------------- launcher ----------------
extern "C" void kernel_launch(void* const* d_in, const int* in_sizes, int n_in,
                              void* d_out, int out_size)
{
    const float* x  = (const float*)d_in[0];
    const float* Wq = (const float*)d_in[1];
    const float* Wk = (const float*)d_in[2];
    const float* Wv = (const float*)d_in[3];
    const float* Wo = (const float*)d_in[4];
    const float* bo = (const float*)d_in[5];
    const float* W1 = (const float*)d_in[6];
    const float* b1 = (const float*)d_in[7];
    const float* W2 = (const float*)d_in[8];
    const float* b2 = (const float*)d_in[9];
    const float* g1 = (const float*)d_in[10];
    const float* be1= (const float*)d_in[11];
    const float* g2 = (const float*)d_in[12];
    const float* be2= (const float*)d_in[13];
    float* out = (float*)d_out;

    void* sp = nullptr;
    cudaGetSymbolAddress(&sp, g_s);
    unsigned char* b = (unsigned char*)sp;
    __half* p_h   = (__half*)(b + O_H);
    __half* p_h2  = (__half*)(b + O_H2);
    __half* p_ao  = (__half*)(b + O_AO);
    __half* p_ff  = (__half*)(b + O_FF);
    __half* p_q   = (__half*)(b + O_Q);
    __half* p_k   = (__half*)(b + O_K);
    __half* p_vt  = (__half*)(b + O_VT);
    __half* p_wqkv= (__half*)(b + O_WQKV);
    __half* p_wot = (__half*)(b + O_WOT);
    __half* p_w1t = (__half*)(b + O_W1T);
    __half* p_w2t = (__half*)(b + O_W2T);
    __half* p_S   = (__half*)(b + O_S);
    float*  p_l   = (float*)(b + O_L);
    float*  p_x2  = (float*)(b + O_X2);
    float*  p_ps  = (float*)(b + O_PS);

    cudaFuncSetAttribute(gemm_mma<0>, cudaFuncAttributeMaxDynamicSharedMemorySize, 65536);
    cudaFuncSetAttribute(gemm_mma<1>, cudaFuncAttributeMaxDynamicSharedMemorySize, 65536);
    cudaFuncSetAttribute(gemm_mma<2>, cudaFuncAttributeMaxDynamicSharedMemorySize, 65536);
    cudaFuncSetAttribute(score_mma,   cudaFuncAttributeMaxDynamicSharedMemorySize, 49152);
    cudaFuncSetAttribute(pv_mma,      cudaFuncAttributeMaxDynamicSharedMemorySize, 49152);

    dim3 b32(32, 32);
    ln_h<<<8192, 256>>>(x, g1, be1, p_h);
    packqkv<<<dim3(16, 2, 24), b32>>>(Wq, Wk, Wv, p_wqkv);
    tr_kernel<<<dim3(16, 16), b32>>>(Wo, p_wot, 512, 512);
    tr_kernel<<<dim3(64, 16), b32>>>(W1, p_w1t, 512, 2048);
    tr_kernel<<<dim3(16, 64), b32>>>(W2, p_w2t, 2048, 512);
    gemm_mma<0><<<dim3(12, 64), 256, 65536>>>(p_h, p_wqkv, 512, nullptr, nullptr,
                                              nullptr, nullptr, p_q, p_k, p_vt);
    score_mma<<<dim3(16, 32), 256, 49152>>>(p_q, p_k, p_S, p_ps);
    combine_sum<<<dim3(8, 32), 256>>>(p_ps, p_l);
    scale_v<<<2048, 256>>>(p_vt, p_l);
    pv_mma<<<dim3(16, 32), 256, 49152>>>(p_S, p_vt, p_ao);
    gemm_mma<1><<<dim3(4, 64), 256, 65536>>>(p_ao, p_wot, 512, bo, x,
                                             p_x2, nullptr, nullptr, nullptr, nullptr);
    ln_h<<<8192, 256>>>(p_x2, g2, be2, p_h2);
    gemm_mma<2><<<dim3(16, 64), 256, 65536>>>(p_h2, p_w1t, 512, b1, nullptr,
                                              nullptr, p_ff, nullptr, nullptr, nullptr);
    gemm_mma<1><<<dim3(4, 64), 256, 65536>>>(p_ff, p_w2t, 2048, b2, p_x2,
                                             out, nullptr, nullptr, nullptr, nullptr);
}

// round 7
// speedup vs baseline: 6.1650x; 1.2083x over previous
#include <cuda_runtime.h>
#include <cuda_fp16.h>
#include <cstdint>
#include <cstddef>

#define TS 2048
#define CE 512
#define DINL __device__ __forceinline__

// ---------------- scratch (bytes) ----------------
constexpr size_t B_ROWC = (size_t)8192 * 512 * 2;
constexpr size_t B_FF   = (size_t)8192 * 2048 * 2;
constexpr size_t B_QKV  = (size_t)32 * 2048 * 64 * 2;
constexpr size_t B_S    = (size_t)32 * 2048 * 2048 * 2;
constexpr size_t B_COL  = (size_t)32 * 2048 * 4;
constexpr size_t O_H    = 0;
constexpr size_t O_H2   = O_H   + B_ROWC;
constexpr size_t O_AO   = O_H2  + B_ROWC;
constexpr size_t O_FF   = O_AO  + B_ROWC;
constexpr size_t O_Q    = O_FF  + B_FF;
constexpr size_t O_K    = O_Q   + B_QKV;
constexpr size_t O_VT   = O_K   + B_QKV;
constexpr size_t O_WQKV = O_VT  + B_QKV;
constexpr size_t O_WOT  = O_WQKV + (size_t)1536*512*2;
constexpr size_t O_W1T  = O_WOT  + (size_t)512*512*2;
constexpr size_t O_W2T  = O_W1T  + (size_t)2048*512*2;
constexpr size_t O_S    = O_W2T  + (size_t)512*2048*2;
constexpr size_t O_L    = O_S   + B_S;
constexpr size_t O_X2   = O_L   + B_COL;
constexpr size_t O_PS   = O_X2  + (size_t)8192*512*4;          // psum [32][32][2048] f32
constexpr size_t SZ_ALL = O_PS  + (size_t)32*32*2048*4;

__device__ __align__(128) unsigned char g_s[SZ_ALL];

// ---------------- helpers ----------------
DINL uint32_t smem_u32(const void* p) {
    uint32_t a;
    asm("{ .reg .u64 t; cvta.to.shared.u64 t, %1; cvt.u32.u64 %0, t; }" : "=r"(a) : "l"(p));
    return a;
}
DINL uint32_t sw128(uint32_t off) { return off ^ ((off >> 3) & 0x70); }

DINL void cp16(uint32_t s, const void* g) {
    asm volatile("cp.async.cg.shared.global [%0], [%1], 16;" :: "r"(s), "l"(g));
}
#define CP_COMMIT() asm volatile("cp.async.commit_group;" ::: "memory")
template<int N> DINL void cp_wait() {
    asm volatile("cp.async.wait_group %0;" :: "n"(N) : "memory");
}

DINL void ldsm4(uint32_t* r, uint32_t a) {
    asm volatile("ldmatrix.sync.aligned.m8n8.x4.shared.b16 {%0,%1,%2,%3}, [%4];"
        : "=r"(r[0]), "=r"(r[1]), "=r"(r[2]), "=r"(r[3]) : "r"(a));
}
DINL void mma16816(float* d, const uint32_t* a, const uint32_t* b) {
    asm volatile("mma.sync.aligned.m16n8k16.row.col.f32.f16.f16.f32 "
        "{%0,%1,%2,%3},{%4,%5,%6,%7},{%8,%9},{%0,%1,%2,%3};"
        : "+f"(d[0]), "+f"(d[1]), "+f"(d[2]), "+f"(d[3])
        : "r"(a[0]), "r"(a[1]), "r"(a[2]), "r"(a[3]), "r"(b[0]), "r"(b[1]));
}
DINL uint32_t pack2(float a, float b) {
    union { __half2 h; uint32_t u; } cv;
    cv.h = __floats2half2_rn(a, b);
    return cv.u;
}
// async tile copy: NR rows x 64 halves (128B rows), SW128 swizzled; 256 threads
template<int NR>
DINL void ld_tile_cp(const __half* __restrict__ g, int ldh, uint32_t smp, int tid) {
    #pragma unroll
    for (int p = 0; p < NR / 32; p++) {
        int u = tid + (p << 8), r = u >> 3, cc = u & 7;
        cp16(smp + sw128((uint32_t)(r << 7) + (cc << 4)),
             g + (size_t)r * ldh + (cc << 3));
    }
}
DINL void ldA(uint32_t buf, int lane, int m0, int ks, uint32_t a[4][4]) {
    int row = m0 + (lane & 15);
    uint32_t koff = (uint32_t)(ks << 5) + ((lane & 16) ? 16u : 0u);
    #pragma unroll
    for (int mt = 0; mt < 4; mt++)
        ldsm4(a[mt], buf + sw128((uint32_t)((row + mt * 16) << 7) + koff));
}
DINL void ldB16(uint32_t buf, int lane, int n0, int ks, uint32_t b[4]) {
    int row = n0 + (lane & 7) + ((lane & 16) >> 1);
    uint32_t koff = (uint32_t)(ks << 5) + ((lane & 8) << 1);
    ldsm4(b, buf + sw128((uint32_t)(row << 7) + koff));
}
DINL void mma_chunk(uint32_t abuf, uint32_t bbuf, int lane, int wm, int wn, float acc[4][4][4]) {
    #pragma unroll
    for (int ks = 0; ks < 4; ks++) {
        uint32_t a[4][4], b[2][4];
        ldA(abuf, lane, wm * 64, ks, a);
        ldB16(bbuf, lane, wn * 32, ks, b[0]);
        ldB16(bbuf, lane, wn * 32 + 16, ks, b[1]);
        #pragma unroll
        for (int mt = 0; mt < 4; mt++)
            #pragma unroll
            for (int nt = 0; nt < 4; nt++)
                mma16816(acc[mt][nt], a[mt], &b[nt >> 1][(nt & 1) * 2]);
    }
}

// ---------------- LayerNorm fp32 -> fp16 ----------------
__global__ __launch_bounds__(256) void ln_h(
    const float* __restrict__ x, const float* __restrict__ g,
    const float* __restrict__ be, __half* __restrict__ o)
{
    const int row = blockIdx.x, t = threadIdx.x;
    const float* xr = x + (size_t)row * CE;
    float2 ab = *reinterpret_cast<const float2*>(xr + 2 * t);
    float s = ab.x + ab.y, sq = ab.x * ab.x + ab.y * ab.y;
    #pragma unroll
    for (int off = 16; off; off >>= 1) {
        s  += __shfl_xor_sync(~0u, s, off);
        sq += __shfl_xor_sync(~0u, sq, off);
    }
    __shared__ float sh[16];
    if ((t & 31) == 0) { sh[t >> 5] = s; sh[8 + (t >> 5)] = sq; }
    __syncthreads();
    if (t == 0) {
        float S = 0, Q = 0;
        #pragma unroll
        for (int i = 0; i < 8; i++) { S += sh[i]; Q += sh[8 + i]; }
        sh[0] = S; sh[8] = Q;
    }
    __syncthreads();
    float mu = sh[0] * (1.f / 512), var = sh[8] * (1.f / 512) - mu * mu;
    float inv = rsqrtf(var + 1e-5f);
    float o0 = (ab.x - mu) * inv * g[2 * t] + be[2 * t];
    float o1 = (ab.y - mu) * inv * g[2 * t + 1] + be[2 * t + 1];
    *reinterpret_cast<__half2*>(o + (size_t)row * CE + 2 * t) = __floats2half2_rn(o0, o1);
}

// ---------------- weight prep ----------------
__global__ void packqkv(const float* __restrict__ Wq, const float* __restrict__ Wk,
                        const float* __restrict__ Wv, __half* __restrict__ wt)
{
    __shared__ float tl[32][33];
    int c0 = blockIdx.x << 5, d0 = blockIdx.y << 5, z = blockIdx.z;
    int which = z >> 3, h = z & 7;
    const float* W = which == 0 ? Wq : (which == 1 ? Wk : Wv);
    float sc = which == 0 ? 0.04419417382415922f : 1.f;
    tl[threadIdx.y][threadIdx.x] =
        W[((size_t)h * 512 + c0 + threadIdx.y) * 64 + d0 + threadIdx.x] * sc;
    __syncthreads();
    wt[((size_t)(which * 512 + h * 64 + d0 + threadIdx.y)) * 512 + c0 + threadIdx.x] =
        __float2half(tl[threadIdx.x][threadIdx.y]);
}
// one kernel for all three weight transposes (flattened tile index)
__global__ void tr_all(const float* __restrict__ Wo, const float* __restrict__ W1,
                       const float* __restrict__ W2, __half* __restrict__ wot,
                       __half* __restrict__ w1t, __half* __restrict__ w2t)
{
    __shared__ float tl[32][33];
    int bid = blockIdx.x;
    const float* in; __half* out; int K, N, tx_, ty_;
    if (bid < 256)       { in = Wo; out = wot; K = 512;  N = 512;  bid -= 0;    tx_ = bid & 15; ty_ = bid >> 4; }
    else if (bid < 1280) { in = W1; out = w1t; K = 512;  N = 2048; bid -= 256;  tx_ = bid & 63; ty_ = bid >> 6; }
    else                 { in = W2; out = w2t; K = 2048; N = 512;  bid -= 1280; tx_ = bid & 15; ty_ = bid >> 4; }
    int n0 = tx_ << 5, k0 = ty_ << 5;
    tl[threadIdx.y][threadIdx.x] = in[(size_t)(k0 + threadIdx.y) * N + n0 + threadIdx.x];
    __syncthreads();
    out[(size_t)(n0 + threadIdx.y) * K + k0 + threadIdx.x] = __float2half(tl[threadIdx.x][threadIdx.y]);
}

// ---------------- GEMM (cp.async 3-stage) ----------------
template<int MODE>
__global__ __launch_bounds__(256) void gemm_mma(
    const __half* __restrict__ A, const __half* __restrict__ B, int K,
    const float* __restrict__ bias, const float* __restrict__ res,
    float* __restrict__ outf, __half* __restrict__ outh,
    __half* __restrict__ oq, __half* __restrict__ ok2, __half* __restrict__ ov)
{
    extern __shared__ __align__(1024) char sm[];
    const uint32_t sA = smem_u32(sm);
    const uint32_t sB = sA + 49152;
    const int tid = threadIdx.x, lane = tid & 31, w = tid >> 5;
    const int wm = w & 1, wn = w >> 1;
    const int m0 = blockIdx.y << 7, n0 = blockIdx.x << 7;
    const __half* Ab = A + (size_t)m0 * K;
    const __half* Bb = B + (size_t)n0 * K;
    float acc[4][4][4];
    #pragma unroll
    for (int i = 0; i < 4; i++)
        #pragma unroll
        for (int j = 0; j < 4; j++)
            #pragma unroll
            for (int e = 0; e < 4; e++) acc[i][j][e] = 0.f;

    const int nc = K >> 6;
    ld_tile_cp<128>(Ab, K, sA, tid);
    ld_tile_cp<128>(Bb, K, sB, tid);
    CP_COMMIT();
    if (nc > 1) {
        ld_tile_cp<128>(Ab + 64, K, sA + 16384, tid);
        ld_tile_cp<128>(Bb + 64, K, sB + 16384, tid);
        CP_COMMIT();
    }
    for (int c = 0; c < nc; c++) {
        if (c + 1 < nc) cp_wait<1>(); else cp_wait<0>();
        __syncthreads();
        if (c + 2 < nc) {
            const uint32_t st = (uint32_t)((c + 2) % 3) << 14;
            ld_tile_cp<128>(Ab + ((c + 2) << 6), K, sA + st, tid);
            ld_tile_cp<128>(Bb + ((c + 2) << 6), K, sB + st, tid);
            CP_COMMIT();
        }
        const uint32_t cur = (uint32_t)(c % 3) << 14;
        mma_chunk(sA + cur, sB + cur, lane, wm, wn, acc);
    }
    const int gm = lane >> 2, gn2 = (lane & 3) << 1;
    #pragma unroll
    for (int mt = 0; mt < 4; mt++) {
        #pragma unroll
        for (int nt = 0; nt < 4; nt++) {
            #pragma unroll
            for (int hf = 0; hf < 2; hf++) {
                const int m = m0 + wm * 64 + mt * 16 + gm + hf * 8;
                const int n = n0 + wn * 32 + nt * 8 + gn2;
                float v0 = acc[mt][nt][hf * 2 + 0], v1 = acc[mt][nt][hf * 2 + 1];
                if (MODE == 1) {
                    size_t ri = (size_t)m * 512 + n;
                    float2 o = { v0 + bias[n] + res[ri], v1 + bias[n + 1] + res[ri + 1] };
                    *reinterpret_cast<float2*>(outf + ri) = o;
                } else if (MODE == 2) {
                    *reinterpret_cast<uint32_t*>(outh + (size_t)m * 2048 + n) =
                        pack2(fmaxf(v0 + bias[n], 0.f), fmaxf(v1 + bias[n + 1], 0.f));
                } else {
                    int which = n0 >> 9;
                    int hh = (n & 511) >> 6, d = n & 63;
                    int b = m >> 11, t2 = m & 2047;
                    int bh = (b << 3) + hh;
                    if (which < 2) {
                        __half* dst = which == 0 ? oq : ok2;
                        *reinterpret_cast<uint32_t*>(dst + ((size_t)bh * 2048 + t2) * 64 + d) =
                            pack2(v0, v1);
                    } else {
                        ov[((size_t)bh * 64 + d) * 2048 + t2]     = __float2half(v0);
                        ov[((size_t)bh * 64 + d + 1) * 2048 + t2] = __float2half(v1);
                    }
                }
            }
        }
    }
}

// ------- scores: E = exp(q.k) masked, + per-64row column-sum partials -------
__global__ __launch_bounds__(256) void score_mma(
    const __half* __restrict__ q, const __half* __restrict__ k,
    __half* __restrict__ S, float* __restrict__ psum)
{
    extern __shared__ __align__(1024) char sm[];
    const uint32_t sQ = smem_u32(sm);
    const uint32_t sK = sQ + 16384;
    const int tid = threadIdx.x, lane = tid & 31, w = tid >> 5;
    const int wm = w & 1, wn = w >> 1;
    const int tt = (int)gridDim.x - 1 - (int)blockIdx.x, bh = blockIdx.y;
    const __half* qb = q + ((size_t)bh * TS + (size_t)tt * 128) * 64;
    const __half* kb = k + (size_t)bh * TS * 64;
    __half* Sb = S + (size_t)bh * TS * TS;

    ld_tile_cp<128>(qb, 64, sQ, tid);
    ld_tile_cp<128>(kb, 64, sK, tid);
    CP_COMMIT();
    if (tt >= 1) {
        ld_tile_cp<128>(kb + 8192, 64, sK + 16384, tid);
        CP_COMMIT();
    }
    const int gm = lane >> 2, gn2 = (lane & 3) << 1;
    for (int st = 0; st <= tt; st++) {
        if (st < tt) cp_wait<1>(); else cp_wait<0>();
        __syncthreads();
        if (st + 2 <= tt) {
            ld_tile_cp<128>(kb + (size_t)(st + 2) * 8192, 64,
                            sK + ((uint32_t)((st + 2) % 3) << 14), tid);
            CP_COMMIT();
        }
        float acc[4][4][4];
        #pragma unroll
        for (int i = 0; i < 4; i++)
            #pragma unroll
            for (int j = 0; j < 4; j++)
                #pragma unroll
                for (int e = 0; e < 4; e++) acc[i][j][e] = 0.f;
        mma_chunk(sQ, sK + ((uint32_t)(st % 3) << 14), lane, wm, wn, acc);
        #pragma unroll
        for (int nt = 0; nt < 4; nt++) {
            float cs0 = 0.f, cs1 = 0.f;
            const int s = st * 128 + wn * 32 + nt * 8 + gn2;
            #pragma unroll
            for (int mt = 0; mt < 4; mt++) {
                #pragma unroll
                for (int hf = 0; hf < 2; hf++) {
                    const int t2 = tt * 128 + wm * 64 + mt * 16 + gm + hf * 8;
                    float e0 = __expf(acc[mt][nt][hf * 2 + 0]);
                    float e1 = __expf(acc[mt][nt][hf * 2 + 1]);
                    if (st == tt) {
                        if (s > t2)     e0 = 0.f;
                        if (s + 1 > t2) e1 = 0.f;
                    }
                    cs0 += e0; cs1 += e1;
                    *reinterpret_cast<uint32_t*>(Sb + (size_t)t2 * TS + s) = pack2(e0, e1);
                }
            }
            #pragma unroll
            for (int o = 4; o < 32; o <<= 1) {
                cs0 += __shfl_xor_sync(~0u, cs0, o);
                cs1 += __shfl_xor_sync(~0u, cs1, o);
            }
            if (lane < 4) {
                float* pm = psum + ((size_t)(tt * 2 + wm) * 32 + bh) * TS + s;
                pm[0] = cs0; pm[1] = cs1;
            }
        }
    }
}

// ---------------- combine column sums -> 1/l ----------------
__global__ __launch_bounds__(256) void combine_sum(
    const float* __restrict__ psum, float* __restrict__ lc)
{
    const int bh = blockIdx.y, s = blockIdx.x * 256 + threadIdx.x;
    const int p0 = (s >> 7) << 1;
    float l = 0.f;
    for (int p = p0; p < 32; p++)
        l += psum[((size_t)p * 32 + bh) * TS + s];
    lc[(size_t)bh * TS + s] = 1.f / l;
}

// ---------------- fold linv into Vt rows (in place) ----------------
__global__ __launch_bounds__(256) void scale_v(
    __half* __restrict__ vt, const float* __restrict__ lc)
{
    const int row = blockIdx.x;           // bh*64 + d
    const int bh = row >> 6;
    __half2* vp = reinterpret_cast<__half2*>(vt + (size_t)row * TS);
    const float2* lp = reinterpret_cast<const float2*>(lc + (size_t)bh * TS);
    #pragma unroll
    for (int i = threadIdx.x; i < 1024; i += 256) {
        float2 l = lp[i];
        float2 v = __half22float2(vp[i]);
        vp[i] = __floats2half2_rn(v.x * l.x, v.y * l.y);
    }
}

// ---------------- PV: plain GEMM out[128,64] = E @ Vs^T (cp.async 3-stage) --
__global__ __launch_bounds__(256) void pv_mma(
    const __half* __restrict__ S, const __half* __restrict__ Vs,
    __half* __restrict__ ao)
{
    extern __shared__ __align__(1024) char sm[];
    const uint32_t sA = smem_u32(sm);
    const uint32_t sB = sA + 49152;
    const int tid = threadIdx.x, lane = tid & 31, w = tid >> 5;
    const int wm = w & 1, wn = w >> 1;
    const int tt = (int)gridDim.x - 1 - (int)blockIdx.x, bh = blockIdx.y;
    const __half* Ab = S + ((size_t)bh * TS + (size_t)tt * 128) * TS;
    const __half* Bb = Vs + (size_t)bh * 64 * TS;

    float acc[4][2][4];
    #pragma unroll
    for (int i = 0; i < 4; i++)
        #pragma unroll
        for (int j = 0; j < 2; j++)
            #pragma unroll
            for (int e = 0; e < 4; e++) acc[i][j][e] = 0.f;

    const int nch = 2 * (tt + 1);
    ld_tile_cp<128>(Ab, TS, sA, tid);
    ld_tile_cp<64>(Bb, TS, sB, tid);
    CP_COMMIT();
    ld_tile_cp<128>(Ab + 64, TS, sA + 16384, tid);
    ld_tile_cp<64>(Bb + 64, TS, sB + 8192, tid);
    CP_COMMIT();
    for (int c = 0; c < nch; c++) {
        if (c + 1 < nch) cp_wait<1>(); else cp_wait<0>();
        __syncthreads();
        if (c + 2 < nch) {
            const int st = (c + 2) % 3;
            ld_tile_cp<128>(Ab + (c + 2) * 64, TS, sA + ((uint32_t)st << 14), tid);
            ld_tile_cp<64>(Bb + (c + 2) * 64, TS, sB + (uint32_t)st * 8192, tid);
            CP_COMMIT();
        }
        const uint32_t ab = sA + ((uint32_t)(c % 3) << 14);
        const uint32_t bb = sB + (uint32_t)(c % 3) * 8192;
        #pragma unroll
        for (int ks = 0; ks < 4; ks++) {
            uint32_t a[4][4], b[4];
            ldA(ab, lane, wm * 64, ks, a);
            ldB16(bb, lane, wn * 16, ks, b);
            #pragma unroll
            for (int mt = 0; mt < 4; mt++) {
                mma16816(acc[mt][0], a[mt], &b[0]);
                mma16816(acc[mt][1], a[mt], &b[2]);
            }
        }
    }
    const int gm = lane >> 2, gn2 = (lane & 3) << 1;
    #pragma unroll
    for (int mt = 0; mt < 4; mt++) {
        #pragma unroll
        for (int nt = 0; nt < 2; nt++) {
            #pragma unroll
            for (int hf = 0; hf < 2; hf++) {
                const int t2 = tt * 128 + wm * 64 + mt * 16 + gm + hf * 8;
                const int n = wn * 16 + nt * 8 + gn2;
                *reinterpret_cast<uint32_t*>(
                    ao + ((size_t)(bh >> 3) * TS + t2) * 512 + (bh & 7) * 64 + n) =
                    pack2(acc[mt][nt][hf * 2 + 0], acc[mt][nt][hf * 2 + 1]);
            }
        }
    }
}

// ---------------- launcher ----------------
extern "C" void kernel_launch(void* const* d_in, const int* in_sizes, int n_in,
                              void* d_out, int out_size)
{
    const float* x  = (const float*)d_in[0];
    const float* Wq = (const float*)d_in[1];
    const float* Wk = (const float*)d_in[2];
    const float* Wv = (const float*)d_in[3];
    const float* Wo = (const float*)d_in[4];
    const float* bo = (const float*)d_in[5];
    const float* W1 = (const float*)d_in[6];
    const float* b1 = (const float*)d_in[7];
    const float* W2 = (const float*)d_in[8];
    const float* b2 = (const float*)d_in[9];
    const float* g1 = (const float*)d_in[10];
    const float* be1= (const float*)d_in[11];
    const float* g2 = (const float*)d_in[12];
    const float* be2= (const float*)d_in[13];
    float* out = (float*)d_out;

    void* sp = nullptr;
    cudaGetSymbolAddress(&sp, g_s);
    unsigned char* b = (unsigned char*)sp;
    __half* p_h   = (__half*)(b + O_H);
    __half* p_h2  = (__half*)(b + O_H2);
    __half* p_ao  = (__half*)(b + O_AO);
    __half* p_ff  = (__half*)(b + O_FF);
    __half* p_q   = (__half*)(b + O_Q);
    __half* p_k   = (__half*)(b + O_K);
    __half* p_vt  = (__half*)(b + O_VT);
    __half* p_wqkv= (__half*)(b + O_WQKV);
    __half* p_wot = (__half*)(b + O_WOT);
    __half* p_w1t = (__half*)(b + O_W1T);
    __half* p_w2t = (__half*)(b + O_W2T);
    __half* p_S   = (__half*)(b + O_S);
    float*  p_l   = (float*)(b + O_L);
    float*  p_x2  = (float*)(b + O_X2);
    float*  p_ps  = (float*)(b + O_PS);

    cudaFuncSetAttribute(gemm_mma<0>, cudaFuncAttributeMaxDynamicSharedMemorySize, 98304);
    cudaFuncSetAttribute(gemm_mma<1>, cudaFuncAttributeMaxDynamicSharedMemorySize, 98304);
    cudaFuncSetAttribute(gemm_mma<2>, cudaFuncAttributeMaxDynamicSharedMemorySize, 98304);
    cudaFuncSetAttribute(score_mma,   cudaFuncAttributeMaxDynamicSharedMemorySize, 65536);
    cudaFuncSetAttribute(pv_mma,      cudaFuncAttributeMaxDynamicSharedMemorySize, 73728);

    dim3 b32(32, 32);
    ln_h<<<8192, 256>>>(x, g1, be1, p_h);
    packqkv<<<dim3(16, 2, 24), b32>>>(Wq, Wk, Wv, p_wqkv);
    tr_all<<<2304, b32>>>(Wo, W1, W2, p_wot, p_w1t, p_w2t);
    gemm_mma<0><<<dim3(12, 64), 256, 98304>>>(p_h, p_wqkv, 512, nullptr, nullptr,
                                              nullptr, nullptr, p_q, p_k, p_vt);
    score_mma<<<dim3(16, 32), 256, 65536>>>(p_q, p_k, p_S, p_ps);
    combine_sum<<<dim3(8, 32), 256>>>(p_ps, p_l);
    scale_v<<<2048, 256>>>(p_vt, p_l);
    pv_mma<<<dim3(16, 32), 256, 73728>>>(p_S, p_vt, p_ao);
    gemm_mma<1><<<dim3(4, 64), 256, 98304>>>(p_ao, p_wot, 512, bo, x,
                                             p_x2, nullptr, nullptr, nullptr, nullptr);
    ln_h<<<8192, 256>>>(p_x2, g2, be2, p_h2);
    gemm_mma<2><<<dim3(16, 64), 256, 98304>>>(p_h2, p_w1t, 512, b1, nullptr,
                                              nullptr, p_ff, nullptr, nullptr, nullptr);
    gemm_mma<1><<<dim3(4, 64), 256, 98304>>>(p_ff, p_w2t, 2048, b2, p_x2,
                                             out, nullptr, nullptr, nullptr, nullptr);
}